// round 6
// baseline (speedup 1.0000x reference)
#include <cuda_runtime.h>
#include <cuda_fp16.h>
#include <math_constants.h>
#include <cstdint>

#define B_ 2
#define L_ 2048
#define D_ 2048
#define H_ 16
#define KV_ 4
#define HD_ 128
#define REP_ (H_ / KV_)

// Scratch (allocation-free rule: device globals)
__device__ float g_q[(size_t)B_ * L_ * D_];             // 32 MB (pre-rope q)
__device__ float g_k[(size_t)B_ * L_ * KV_ * HD_];      // 8 MB  (pre-rope k)
__device__ __half g_qh[(size_t)B_ * L_ * D_];           // 16 MB (roped q * scale)
__device__ __half g_kh[(size_t)B_ * L_ * KV_ * HD_];    // 4 MB  (roped k)
__device__ __half g_vh[(size_t)B_ * L_ * KV_ * HD_];    // 4 MB
__device__ __half g_xh[(size_t)B_ * L_ * D_];           // 16 MB
__device__ __half g_wqh[(size_t)D_ * D_];               // 8 MB
__device__ __half g_wkh[(size_t)KV_ * HD_ * D_];        // 2 MB
__device__ __half g_wvh[(size_t)KV_ * HD_ * D_];        // 2 MB
__device__ __half g_woh[(size_t)D_ * D_];               // 8 MB
__device__ __half g_aoh[(size_t)B_ * L_ * D_];          // 16 MB

// ---------------------------------------------------------------------------
// helpers
// ---------------------------------------------------------------------------
__device__ __forceinline__ void mma_f16(float c[4], const unsigned a[4],
                                        const unsigned b[2]) {
  asm volatile(
      "mma.sync.aligned.m16n8k16.row.col.f32.f16.f16.f32 "
      "{%0,%1,%2,%3}, {%4,%5,%6,%7}, {%8,%9}, {%0,%1,%2,%3};"
      : "+f"(c[0]), "+f"(c[1]), "+f"(c[2]), "+f"(c[3])
      : "r"(a[0]), "r"(a[1]), "r"(a[2]), "r"(a[3]), "r"(b[0]), "r"(b[1]));
}

__device__ __forceinline__ void ldmx4(unsigned r[4], uint32_t addr) {
  asm volatile(
      "ldmatrix.sync.aligned.m8n8.x4.shared.b16 {%0,%1,%2,%3}, [%4];"
      : "=r"(r[0]), "=r"(r[1]), "=r"(r[2]), "=r"(r[3]) : "r"(addr));
}

__device__ __forceinline__ void ldmx2t(unsigned& r0, unsigned& r1,
                                       uint32_t addr) {
  asm volatile(
      "ldmatrix.sync.aligned.m8n8.x2.trans.shared.b16 {%0,%1}, [%2];"
      : "=r"(r0), "=r"(r1) : "r"(addr));
}

__device__ __forceinline__ uint32_t smem_u32(const void* p) {
  uint32_t a;
  asm("{ .reg .u64 t; cvta.to.shared.u64 t, %1; cvt.u32.u64 %0, t; }"
      : "=r"(a) : "l"(p));
  return a;
}

__device__ __forceinline__ void cp_async16(uint32_t dst, const void* src) {
  asm volatile("cp.async.cg.shared.global [%0], [%1], 16;\n"
               :: "r"(dst), "l"(src) : "memory");
}

__device__ __forceinline__ void st2(float* p, float a, float b) {
  *(float2*)p = make_float2(a, b);
}
__device__ __forceinline__ void st2(__half* p, float a, float b) {
  *(__half2*)p = __floats2half2_rn(a, b);
}

// ---------------------------------------------------------------------------
// fp16 tensor-core GEMM: C[M,N] = A[M,Kd] * W[N,Kd]^T (A,W fp16; C fp32/fp16)
// 128x128 CTA tile, BK=32, 256 threads (8 warps 2x4), warp tile 64x32,
// m16n8k16 mma + ldmatrix, 3-stage cp.async ring (dynamic smem).
// ---------------------------------------------------------------------------
#define FBM 128
#define FBN 128
#define FBK 32
#define FLD 40   // halfs per row (32 + 8 pad)
#define GSTG (FBM * FLD)               // halfs per stage per matrix
#define GT_SMEM (3 * GSTG * 2 * 2)     // bytes: 3 stages x (A+B)

template <typename OT>
__global__ __launch_bounds__(256, 2)
void gemm_f16(const __half* __restrict__ A, const __half* __restrict__ W,
              OT* __restrict__ C, int M, int N, int Kd) {
  extern __shared__ __half dsm[];
  __half* Asm = dsm;                 // [3][FBM][FLD]
  __half* Bsm = dsm + 3 * GSTG;      // [3][FBM][FLD]
  const int bm = blockIdx.y * FBM;
  const int bn = blockIdx.x * FBN;
  const int tid = threadIdx.x;
  const int warp = tid >> 5;
  const int lane = tid & 31;
  const int m0 = (warp >> 2) * 64;
  const int n0 = (warp & 3) * 32;

  const uint32_t sbA = smem_u32(Asm);
  const uint32_t sbB = smem_u32(Bsm);
  const uint32_t STB = GSTG * 2;     // stage bytes

  // cp.async map: 512 chunks of 16B per matrix per stage, 2 per thread
  const int r0c = tid >> 2, c0c = (tid & 3);
  const int r1c = (tid + 256) >> 2, c1c = ((tid + 256) & 3);
  const uint32_t d0 = (uint32_t)(r0c * FLD * 2 + c0c * 16);
  const uint32_t d1 = (uint32_t)(r1c * FLD * 2 + c1c * 16);

  const __half* Ab = A + (size_t)bm * Kd;
  const __half* Wb = W + (size_t)bn * Kd;
  const size_t s0 = (size_t)r0c * Kd + c0c * 8;
  const size_t s1 = (size_t)r1c * Kd + c1c * 8;

#define F16_LOAD(st, k0)                                                    \
  do {                                                                      \
    cp_async16(sbA + (st) * STB + d0, Ab + s0 + (k0));                      \
    cp_async16(sbA + (st) * STB + d1, Ab + s1 + (k0));                      \
    cp_async16(sbB + (st) * STB + d0, Wb + s0 + (k0));                      \
    cp_async16(sbB + (st) * STB + d1, Wb + s1 + (k0));                      \
    asm volatile("cp.async.commit_group;" ::: "memory");                    \
  } while (0)

  const uint32_t a_off =
      (uint32_t)(((m0 + (lane & 15)) * FLD + ((lane >> 4) << 3)) * 2);
  const uint32_t b_off =
      (uint32_t)(((n0 + (lane & 7) + ((lane >> 4) & 1) * 8) * FLD +
                  ((lane >> 3) & 1) * 8) * 2);

  float acc[4][4][4];
#pragma unroll
  for (int i = 0; i < 4; i++)
#pragma unroll
    for (int j = 0; j < 4; j++)
#pragma unroll
      for (int q = 0; q < 4; q++) acc[i][j][q] = 0.f;

  const int nk = Kd / FBK;
  F16_LOAD(0, 0);
  F16_LOAD(1, FBK);

  for (int t = 0; t < nk; t++) {
    const int buf = t % 3;
    if (t + 2 < nk) {
      F16_LOAD((t + 2) % 3, (t + 2) * FBK);
      asm volatile("cp.async.wait_group 2;" ::: "memory");
    } else if (t + 1 < nk) {
      asm volatile("cp.async.wait_group 1;" ::: "memory");
    } else {
      asm volatile("cp.async.wait_group 0;" ::: "memory");
    }
    __syncthreads();

    const uint32_t aB = sbA + buf * STB + a_off;
    const uint32_t bB = sbB + buf * STB + b_off;
#pragma unroll
    for (int ks = 0; ks < 2; ks++) {
      const uint32_t ksb = ks * 32;  // 16 halfs
      unsigned a[4][4], b[4][2];
#pragma unroll
      for (int i = 0; i < 4; i++) ldmx4(a[i], aB + i * (16 * FLD * 2) + ksb);
      {
        unsigned t4[4];
        ldmx4(t4, bB + ksb);
        b[0][0] = t4[0]; b[0][1] = t4[1]; b[1][0] = t4[2]; b[1][1] = t4[3];
        ldmx4(t4, bB + 16 * FLD * 2 + ksb);
        b[2][0] = t4[0]; b[2][1] = t4[1]; b[3][0] = t4[2]; b[3][1] = t4[3];
      }
#pragma unroll
      for (int i = 0; i < 4; i++)
#pragma unroll
        for (int j = 0; j < 4; j++) mma_f16(acc[i][j], a[i], b[j]);
    }
    __syncthreads();
  }

  const int g = lane >> 2;
  const int tig = lane & 3;
#pragma unroll
  for (int i = 0; i < 4; i++) {
#pragma unroll
    for (int j = 0; j < 4; j++) {
      const size_t row1 = (size_t)(bm + m0 + i * 16 + g);
      const int col = bn + n0 + j * 8 + tig * 2;
      st2(C + row1 * N + col, acc[i][j][0], acc[i][j][1]);
      st2(C + (row1 + 8) * N + col, acc[i][j][2], acc[i][j][3]);
    }
  }
}

// ---------------------------------------------------------------------------
// fp32 -> fp16 convert
// ---------------------------------------------------------------------------
__global__ void cvt_f16_kernel(const float* __restrict__ src,
                               __half* __restrict__ dst, int n4) {
  int i = blockIdx.x * blockDim.x + threadIdx.x;
  if (i >= n4) return;
  float4 v = ((const float4*)src)[i];
  __half2 lo = __floats2half2_rn(v.x, v.y);
  __half2 hi = __floats2half2_rn(v.z, v.w);
  ((uint2*)dst)[i] = make_uint2(*(unsigned*)&lo, *(unsigned*)&hi);
}

// ---------------------------------------------------------------------------
// RoPE: fp32 in -> fp16 out, optional scale folded in.
// ---------------------------------------------------------------------------
__global__ void rope_h_kernel(const float* __restrict__ in,
                              __half* __restrict__ out, int nh, int total,
                              float sc) {
  int idx = blockIdx.x * blockDim.x + threadIdx.x;
  if (idx >= total) return;
  int i = idx & (HD_ / 2 - 1);
  int t = idx >> 6;
  int h = t % nh;
  int bl = t / nh;
  int pos = bl & (L_ - 1);
  float inv_freq = expf(-(float)i * (2.0f / HD_) * 9.210340371976184f);
  float ang = (float)pos * inv_freq;
  float s, c;
  sincosf(ang, &s, &c);
  size_t base = ((size_t)bl * nh + h) * HD_ + 2 * i;
  float x1 = in[base], x2 = in[base + 1];
  *(__half2*)(out + base) =
      __floats2half2_rn((x1 * c - x2 * s) * sc, (x1 * s + x2 * c) * sc);
}

// ---------------------------------------------------------------------------
// fp16 tensor-core causal flash attention, online softmax.
// CTA: 4 warps x 16 q-rows = 64 rows. Key tiles of 32, double-buffered
// cp.async K/V staging. K B-frags via contiguous LDS.32; V via ldmatrix.trans.
// ---------------------------------------------------------------------------
#define AT_TK 32
#define AT_WQ 16
#define AT_WARPS 4
#define AT_QB (AT_WQ * AT_WARPS)   // 64
#define KLD 136                    // halfs per K/V smem row (128 + 8)

__global__ __launch_bounds__(128, 3)
void flash_attn_f16(const __half* __restrict__ Qh, const __half* __restrict__ Kh,
                    const __half* __restrict__ Vh, __half* __restrict__ O) {
  __shared__ __half Ks[2][AT_TK][KLD];
  __shared__ __half Vs[2][AT_TK][KLD];
  __shared__ unsigned Ps[AT_WARPS][16][20];

  const int b = blockIdx.z;
  const int h = blockIdx.y;
  const int r0 = blockIdx.x * AT_QB;
  const int kvh = h / REP_;
  const int warp = threadIdx.x >> 5;
  const int lane = threadIdx.x & 31;
  const int g = lane >> 2;
  const int tig = lane & 3;
  const int row0 = r0 + warp * AT_WQ;

  const uint32_t sKs = smem_u32(&Ks[0][0][0]);
  const uint32_t sVs = smem_u32(&Vs[0][0][0]);
  const uint32_t KVB = AT_TK * KLD * 2;  // bytes per buffer

  // persistent Q fragments (scale already folded by rope): qa[kslab][4]
  unsigned qa[8][4];
  {
    const __half* Qb = Qh + ((size_t)(b * L_ + row0) * H_ + h) * HD_;
#pragma unroll
    for (int s = 0; s < 8; s++) {
      const int k0 = s * 16 + 2 * tig;
      qa[s][0] = *(const unsigned*)(Qb + (size_t)g * D_ + k0);
      qa[s][1] = *(const unsigned*)(Qb + (size_t)(g + 8) * D_ + k0);
      qa[s][2] = *(const unsigned*)(Qb + (size_t)g * D_ + k0 + 8);
      qa[s][3] = *(const unsigned*)(Qb + (size_t)(g + 8) * D_ + k0 + 8);
    }
  }

  float m0v = -CUDART_INF_F, m1v = -CUDART_INF_F;
  float l0 = 0.f, l1 = 0.f;
  float oa[16][4];
#pragma unroll
  for (int j = 0; j < 16; j++)
#pragma unroll
    for (int q = 0; q < 4; q++) oa[j][q] = 0.f;

  // staging map: 512 16B chunks per matrix, 4 per thread each
  uint32_t kdst[4];
  size_t ksrc[4];
#pragma unroll
  for (int i = 0; i < 4; i++) {
    int e = threadIdx.x + i * 128;
    int row = e >> 4, c = e & 15;
    kdst[i] = (uint32_t)(row * (KLD * 2) + c * 16);
    ksrc[i] = ((size_t)(b * L_ + row) * KV_ + kvh) * HD_ + c * 8;
  }

#define KV_LOADT(st, t0)                                                    \
  do {                                                                      \
    _Pragma("unroll")                                                       \
    for (int i = 0; i < 4; i++) {                                           \
      size_t sofs = ksrc[i] + (size_t)(t0) * (KV_ * HD_);                   \
      cp_async16(sKs + (st) * KVB + kdst[i], Kh + sofs);                    \
      cp_async16(sVs + (st) * KVB + kdst[i], Vh + sofs);                    \
    }                                                                       \
    asm volatile("cp.async.commit_group;" ::: "memory");                    \
  } while (0)

  const int tmax = row0 + AT_WQ - 1;
  const int t_end = r0 + AT_QB - 1;

  KV_LOADT(0, 0);

  for (int t0 = 0; t0 <= t_end; t0 += AT_TK) {
    const int buf = (t0 >> 5) & 1;
    if (t0 + AT_TK <= t_end) {
      KV_LOADT(buf ^ 1, t0 + AT_TK);
      asm volatile("cp.async.wait_group 1;" ::: "memory");
    } else {
      asm volatile("cp.async.wait_group 0;" ::: "memory");
    }
    __syncthreads();

    if (t0 <= tmax) {
      // ---- S = Q K^T : 4 n-tiles (8 keys) x 8 k16-slabs ----
      float sf[4][4];
#pragma unroll
      for (int j = 0; j < 4; j++)
#pragma unroll
        for (int q = 0; q < 4; q++) sf[j][q] = 0.f;

#pragma unroll
      for (int s = 0; s < 8; s++) {
        const int kb = s * 16 + 2 * tig;
        unsigned bk[4][2];
#pragma unroll
        for (int j = 0; j < 4; j++) {
          bk[j][0] = *(const unsigned*)&Ks[buf][j * 8 + g][kb];
          bk[j][1] = *(const unsigned*)&Ks[buf][j * 8 + g][kb + 8];
        }
#pragma unroll
        for (int j = 0; j < 4; j++) mma_f16(sf[j], qa[s], bk[j]);
      }

      // ---- causal mask ----
      if (t0 + AT_TK - 1 > row0) {
#pragma unroll
        for (int j = 0; j < 4; j++) {
          const int col = t0 + j * 8 + 2 * tig;
          if (col > row0 + g) sf[j][0] = -CUDART_INF_F;
          if (col + 1 > row0 + g) sf[j][1] = -CUDART_INF_F;
          if (col > row0 + g + 8) sf[j][2] = -CUDART_INF_F;
          if (col + 1 > row0 + g + 8) sf[j][3] = -CUDART_INF_F;
        }
      }

      // ---- online softmax ----
      float tm0 = sf[0][0], tm1 = sf[0][2];
#pragma unroll
      for (int j = 0; j < 4; j++) {
        tm0 = fmaxf(tm0, fmaxf(sf[j][0], sf[j][1]));
        tm1 = fmaxf(tm1, fmaxf(sf[j][2], sf[j][3]));
      }
      tm0 = fmaxf(tm0, __shfl_xor_sync(0xffffffffu, tm0, 1));
      tm0 = fmaxf(tm0, __shfl_xor_sync(0xffffffffu, tm0, 2));
      tm1 = fmaxf(tm1, __shfl_xor_sync(0xffffffffu, tm1, 1));
      tm1 = fmaxf(tm1, __shfl_xor_sync(0xffffffffu, tm1, 2));

      const float mn0 = fmaxf(m0v, tm0);
      const float mn1 = fmaxf(m1v, tm1);
      const float cr0 = __expf(m0v - mn0);
      const float cr1 = __expf(m1v - mn1);

      float ps0 = 0.f, ps1 = 0.f;
#pragma unroll
      for (int j = 0; j < 4; j++) {
        sf[j][0] = __expf(sf[j][0] - mn0);
        sf[j][1] = __expf(sf[j][1] - mn0);
        sf[j][2] = __expf(sf[j][2] - mn1);
        sf[j][3] = __expf(sf[j][3] - mn1);
        ps0 += sf[j][0] + sf[j][1];
        ps1 += sf[j][2] + sf[j][3];
      }
      ps0 += __shfl_xor_sync(0xffffffffu, ps0, 1);
      ps0 += __shfl_xor_sync(0xffffffffu, ps0, 2);
      ps1 += __shfl_xor_sync(0xffffffffu, ps1, 1);
      ps1 += __shfl_xor_sync(0xffffffffu, ps1, 2);

      l0 = l0 * cr0 + ps0;
      l1 = l1 * cr1 + ps1;
      m0v = mn0;
      m1v = mn1;

#pragma unroll
      for (int j2 = 0; j2 < 16; j2++) {
        oa[j2][0] *= cr0; oa[j2][1] *= cr0;
        oa[j2][2] *= cr1; oa[j2][3] *= cr1;
      }

      // ---- P (fp16) to per-warp smem ----
#pragma unroll
      for (int j = 0; j < 4; j++) {
        __half2 p0 = __floats2half2_rn(sf[j][0], sf[j][1]);
        __half2 p1 = __floats2half2_rn(sf[j][2], sf[j][3]);
        Ps[warp][g][j * 4 + tig] = *(unsigned*)&p0;
        Ps[warp][g + 8][j * 4 + tig] = *(unsigned*)&p1;
      }
      __syncwarp();

      // ---- O += P V : 2 k16-slabs x 16 d-tiles, V via ldmatrix.trans ----
#pragma unroll
      for (int s = 0; s < 2; s++) {
        unsigned pa[4];
        pa[0] = Ps[warp][g][s * 8 + tig];
        pa[1] = Ps[warp][g + 8][s * 8 + tig];
        pa[2] = Ps[warp][g][s * 8 + tig + 4];
        pa[3] = Ps[warp][g + 8][s * 8 + tig + 4];
        const uint32_t vrow =
            sVs + buf * KVB + (s * 16 + (lane & 15)) * (KLD * 2);
#pragma unroll
        for (int j2 = 0; j2 < 16; j2++) {
          unsigned bv[2];
          ldmx2t(bv[0], bv[1], vrow + j2 * 16);
          mma_f16(oa[j2], pa, bv);
        }
      }
    }
    __syncthreads();
  }

  const float inv0 = 1.0f / l0;
  const float inv1 = 1.0f / l1;
  __half* Ob = O + ((size_t)(b * L_ + row0) * H_ + h) * HD_;
#pragma unroll
  for (int j2 = 0; j2 < 16; j2++) {
    const int col = j2 * 8 + 2 * tig;
    *(__half2*)(Ob + (size_t)g * D_ + col) =
        __floats2half2_rn(oa[j2][0] * inv0, oa[j2][1] * inv0);
    *(__half2*)(Ob + (size_t)(g + 8) * D_ + col) =
        __floats2half2_rn(oa[j2][2] * inv1, oa[j2][3] * inv1);
  }
}

// ---------------------------------------------------------------------------
extern "C" void kernel_launch(void* const* d_in, const int* in_sizes, int n_in,
                              void* d_out, int out_size) {
  (void)in_sizes; (void)n_in; (void)out_size;
  const float* x  = (const float*)d_in[0];
  const float* wq = (const float*)d_in[1];
  const float* wk = (const float*)d_in[2];
  const float* wv = (const float*)d_in[3];
  const float* wo = (const float*)d_in[4];
  float* out = (float*)d_out;

  float *q, *k;
  __half *qh, *kh, *vh, *xh, *wqh, *wkh, *wvh, *woh, *aoh;
  cudaGetSymbolAddress((void**)&q, g_q);
  cudaGetSymbolAddress((void**)&k, g_k);
  cudaGetSymbolAddress((void**)&qh, g_qh);
  cudaGetSymbolAddress((void**)&kh, g_kh);
  cudaGetSymbolAddress((void**)&vh, g_vh);
  cudaGetSymbolAddress((void**)&xh, g_xh);
  cudaGetSymbolAddress((void**)&wqh, g_wqh);
  cudaGetSymbolAddress((void**)&wkh, g_wkh);
  cudaGetSymbolAddress((void**)&wvh, g_wvh);
  cudaGetSymbolAddress((void**)&woh, g_woh);
  cudaGetSymbolAddress((void**)&aoh, g_aoh);

  cudaFuncSetAttribute(gemm_f16<float>,
                       cudaFuncAttributeMaxDynamicSharedMemorySize, GT_SMEM);
  cudaFuncSetAttribute(gemm_f16<__half>,
                       cudaFuncAttributeMaxDynamicSharedMemorySize, GT_SMEM);

  const int M = B_ * L_;  // 4096

  // fp16 conversion of GEMM operands
  {
    int n4;
    n4 = (B_ * L_ * D_) / 4;
    cvt_f16_kernel<<<(n4 + 255) / 256, 256>>>(x, xh, n4);
    n4 = (D_ * D_) / 4;
    cvt_f16_kernel<<<(n4 + 255) / 256, 256>>>(wq, wqh, n4);
    cvt_f16_kernel<<<(n4 + 255) / 256, 256>>>(wo, woh, n4);
    n4 = (KV_ * HD_ * D_) / 4;
    cvt_f16_kernel<<<(n4 + 255) / 256, 256>>>(wk, wkh, n4);
    cvt_f16_kernel<<<(n4 + 255) / 256, 256>>>(wv, wvh, n4);
  }

  // Q/K/V projections (fp16 mma + ldmatrix, 3-stage)
  gemm_f16<float><<<dim3(D_ / FBN, M / FBM), 256, GT_SMEM>>>(xh, wqh, q, M,
                                                             D_, D_);
  gemm_f16<float><<<dim3((KV_ * HD_) / FBN, M / FBM), 256, GT_SMEM>>>(
      xh, wkh, k, M, KV_ * HD_, D_);
  gemm_f16<__half><<<dim3((KV_ * HD_) / FBN, M / FBM), 256, GT_SMEM>>>(
      xh, wvh, vh, M, KV_ * HD_, D_);

  // RoPE: fp32 -> fp16, q gets softmax scale folded in
  const float scale = 0.088388347648318447f;  // 1/sqrt(128)
  int nq = B_ * L_ * H_ * (HD_ / 2);
  rope_h_kernel<<<nq / 256, 256>>>(q, qh, H_, nq, scale);
  int nk = B_ * L_ * KV_ * (HD_ / 2);
  rope_h_kernel<<<nk / 256, 256>>>(k, kh, KV_, nk, 1.0f);

  // causal attention (fp16 tensor cores)
  flash_attn_f16<<<dim3(L_ / AT_QB, H_, B_), 128>>>(qh, kh, vh, aoh);

  // output projection -> d_out
  gemm_f16<float><<<dim3(D_ / FBN, M / FBM), 256, GT_SMEM>>>(aoh, woh, out, M,
                                                             D_, D_);
}

// round 7
// speedup vs baseline: 1.5040x; 1.5040x over previous
#include <cuda_runtime.h>
#include <cuda_fp16.h>
#include <math_constants.h>
#include <cstdint>

#define B_ 2
#define L_ 2048
#define D_ 2048
#define H_ 16
#define KV_ 4
#define HD_ 128
#define REP_ (H_ / KV_)

// Scratch (allocation-free rule: device globals)
__device__ float g_q[(size_t)B_ * L_ * D_];             // 32 MB (pre-rope q)
__device__ float g_k[(size_t)B_ * L_ * KV_ * HD_];      // 8 MB  (pre-rope k)
__device__ __half g_qh[(size_t)B_ * L_ * D_];           // 16 MB (roped q * scale)
__device__ __half g_kh[(size_t)B_ * L_ * KV_ * HD_];    // 4 MB  (roped k)
__device__ __half g_vh[(size_t)B_ * L_ * KV_ * HD_];    // 4 MB
__device__ __half g_xh[(size_t)B_ * L_ * D_];           // 16 MB
__device__ __half g_wqh[(size_t)D_ * D_];               // 8 MB
__device__ __half g_wkh[(size_t)KV_ * HD_ * D_];        // 2 MB
__device__ __half g_wvh[(size_t)KV_ * HD_ * D_];        // 2 MB
__device__ __half g_woh[(size_t)D_ * D_];               // 8 MB
__device__ __half g_aoh[(size_t)B_ * L_ * D_];          // 16 MB

// ---------------------------------------------------------------------------
// helpers
// ---------------------------------------------------------------------------
__device__ __forceinline__ void mma_f16(float c[4], const unsigned a[4],
                                        const unsigned b[2]) {
  asm volatile(
      "mma.sync.aligned.m16n8k16.row.col.f32.f16.f16.f32 "
      "{%0,%1,%2,%3}, {%4,%5,%6,%7}, {%8,%9}, {%0,%1,%2,%3};"
      : "+f"(c[0]), "+f"(c[1]), "+f"(c[2]), "+f"(c[3])
      : "r"(a[0]), "r"(a[1]), "r"(a[2]), "r"(a[3]), "r"(b[0]), "r"(b[1]));
}

__device__ __forceinline__ void ldmx4(unsigned r[4], uint32_t addr) {
  asm volatile(
      "ldmatrix.sync.aligned.m8n8.x4.shared.b16 {%0,%1,%2,%3}, [%4];"
      : "=r"(r[0]), "=r"(r[1]), "=r"(r[2]), "=r"(r[3]) : "r"(addr));
}

__device__ __forceinline__ void ldmx2t(unsigned& r0, unsigned& r1,
                                       uint32_t addr) {
  asm volatile(
      "ldmatrix.sync.aligned.m8n8.x2.trans.shared.b16 {%0,%1}, [%2];"
      : "=r"(r0), "=r"(r1) : "r"(addr));
}

__device__ __forceinline__ uint32_t smem_u32(const void* p) {
  uint32_t a;
  asm("{ .reg .u64 t; cvta.to.shared.u64 t, %1; cvt.u32.u64 %0, t; }"
      : "=r"(a) : "l"(p));
  return a;
}

__device__ __forceinline__ void cp_async16(uint32_t dst, const void* src) {
  asm volatile("cp.async.cg.shared.global [%0], [%1], 16;\n"
               :: "r"(dst), "l"(src) : "memory");
}

__device__ __forceinline__ void st2(float* p, float a, float b) {
  *(float2*)p = make_float2(a, b);
}
__device__ __forceinline__ void st2(__half* p, float a, float b) {
  *(__half2*)p = __floats2half2_rn(a, b);
}

// ---------------------------------------------------------------------------
// fp16 tensor-core GEMM: C[M,N] = A[M,Kd] * W[N,Kd]^T (A,W fp16; C fp32/fp16)
// EXACT round-5 structure: 128x128 CTA tile, BK=32, 256 threads (8 warps 2x4),
// warp tile 64x32, m16n8k16 + ldmatrix, 2-stage static-smem cp.async pipeline.
// ---------------------------------------------------------------------------
#define FBM 128
#define FBN 128
#define FBK 32
#define FLD 40   // halfs per row (32 + 8 pad)

template <typename OT>
__global__ __launch_bounds__(256, 2)
void gemm_f16(const __half* __restrict__ A, const __half* __restrict__ W,
              OT* __restrict__ C, int M, int N, int Kd) {
  __shared__ __half As[2][FBM][FLD];
  __shared__ __half Bs[2][FBM][FLD];
  const int bm = blockIdx.y * FBM;
  const int bn = blockIdx.x * FBN;
  const int tid = threadIdx.x;
  const int warp = tid >> 5;
  const int lane = tid & 31;
  const int m0 = (warp >> 2) * 64;
  const int n0 = (warp & 3) * 32;

  const uint32_t sbA = smem_u32(&As[0][0][0]);
  const uint32_t sbB = smem_u32(&Bs[0][0][0]);
  const uint32_t BUFB = FBM * FLD * 2;  // bytes per buffer

  // cp.async map: 512 chunks of 16B per matrix per stage, 2 per thread
  const int r0c = tid >> 2, c0c = (tid & 3);
  const int r1c = (tid + 256) >> 2, c1c = ((tid + 256) & 3);
  const uint32_t d0 = (uint32_t)(r0c * FLD * 2 + c0c * 16);
  const uint32_t d1 = (uint32_t)(r1c * FLD * 2 + c1c * 16);

  const __half* Ab = A + (size_t)bm * Kd;
  const __half* Wb = W + (size_t)bn * Kd;
  const size_t s0 = (size_t)r0c * Kd + c0c * 8;
  const size_t s1 = (size_t)r1c * Kd + c1c * 8;

#define F16_LOAD(buf, k0)                                                   \
  do {                                                                      \
    cp_async16(sbA + (buf)*BUFB + d0, Ab + s0 + (k0));                      \
    cp_async16(sbA + (buf)*BUFB + d1, Ab + s1 + (k0));                      \
    cp_async16(sbB + (buf)*BUFB + d0, Wb + s0 + (k0));                      \
    cp_async16(sbB + (buf)*BUFB + d1, Wb + s1 + (k0));                      \
    asm volatile("cp.async.commit_group;" ::: "memory");                    \
  } while (0)

  const uint32_t a_off =
      (uint32_t)(((m0 + (lane & 15)) * FLD + ((lane >> 4) << 3)) * 2);
  const uint32_t b_off =
      (uint32_t)(((n0 + (lane & 7) + ((lane >> 4) & 1) * 8) * FLD +
                  ((lane >> 3) & 1) * 8) * 2);

  float acc[4][4][4];
#pragma unroll
  for (int i = 0; i < 4; i++)
#pragma unroll
    for (int j = 0; j < 4; j++)
#pragma unroll
      for (int q = 0; q < 4; q++) acc[i][j][q] = 0.f;

  const int nk = Kd / FBK;
  F16_LOAD(0, 0);

  for (int t = 0; t < nk; t++) {
    const int buf = t & 1;
    if (t + 1 < nk) {
      F16_LOAD(buf ^ 1, (t + 1) * FBK);
      asm volatile("cp.async.wait_group 1;" ::: "memory");
    } else {
      asm volatile("cp.async.wait_group 0;" ::: "memory");
    }
    __syncthreads();

    const uint32_t aB = sbA + buf * BUFB + a_off;
    const uint32_t bB = sbB + buf * BUFB + b_off;
#pragma unroll
    for (int ks = 0; ks < 2; ks++) {
      const uint32_t ksb = ks * 32;  // 16 halfs
      unsigned a[4][4], b[4][2];
#pragma unroll
      for (int i = 0; i < 4; i++) ldmx4(a[i], aB + i * (16 * FLD * 2) + ksb);
      {
        unsigned t4[4];
        ldmx4(t4, bB + ksb);
        b[0][0] = t4[0]; b[0][1] = t4[1]; b[1][0] = t4[2]; b[1][1] = t4[3];
        ldmx4(t4, bB + 16 * FLD * 2 + ksb);
        b[2][0] = t4[0]; b[2][1] = t4[1]; b[3][0] = t4[2]; b[3][1] = t4[3];
      }
#pragma unroll
      for (int i = 0; i < 4; i++)
#pragma unroll
        for (int j = 0; j < 4; j++) mma_f16(acc[i][j], a[i], b[j]);
    }
    __syncthreads();
  }

  const int g = lane >> 2;
  const int tig = lane & 3;
#pragma unroll
  for (int i = 0; i < 4; i++) {
#pragma unroll
    for (int j = 0; j < 4; j++) {
      const size_t row1 = (size_t)(bm + m0 + i * 16 + g);
      const int col = bn + n0 + j * 8 + tig * 2;
      st2(C + row1 * N + col, acc[i][j][0], acc[i][j][1]);
      st2(C + (row1 + 8) * N + col, acc[i][j][2], acc[i][j][3]);
    }
  }
}

// ---------------------------------------------------------------------------
// fp32 -> fp16 convert
// ---------------------------------------------------------------------------
__global__ void cvt_f16_kernel(const float* __restrict__ src,
                               __half* __restrict__ dst, int n4) {
  int i = blockIdx.x * blockDim.x + threadIdx.x;
  if (i >= n4) return;
  float4 v = ((const float4*)src)[i];
  __half2 lo = __floats2half2_rn(v.x, v.y);
  __half2 hi = __floats2half2_rn(v.z, v.w);
  ((uint2*)dst)[i] = make_uint2(*(unsigned*)&lo, *(unsigned*)&hi);
}

// ---------------------------------------------------------------------------
// RoPE: fp32 in -> fp16 out, optional scale folded in.
// ---------------------------------------------------------------------------
__global__ void rope_h_kernel(const float* __restrict__ in,
                              __half* __restrict__ out, int nh, int total,
                              float sc) {
  int idx = blockIdx.x * blockDim.x + threadIdx.x;
  if (idx >= total) return;
  int i = idx & (HD_ / 2 - 1);
  int t = idx >> 6;
  int h = t % nh;
  int bl = t / nh;
  int pos = bl & (L_ - 1);
  float inv_freq = expf(-(float)i * (2.0f / HD_) * 9.210340371976184f);
  float ang = (float)pos * inv_freq;
  float s, c;
  sincosf(ang, &s, &c);
  size_t base = ((size_t)bl * nh + h) * HD_ + 2 * i;
  float x1 = in[base], x2 = in[base + 1];
  *(__half2*)(out + base) =
      __floats2half2_rn((x1 * c - x2 * s) * sc, (x1 * s + x2 * c) * sc);
}

// ---------------------------------------------------------------------------
// fp16 tensor-core causal flash attention (unchanged from round 6).
// ---------------------------------------------------------------------------
#define AT_TK 32
#define AT_WQ 16
#define AT_WARPS 4
#define AT_QB (AT_WQ * AT_WARPS)   // 64
#define KLD 136                    // halfs per K/V smem row (128 + 8)

__global__ __launch_bounds__(128, 3)
void flash_attn_f16(const __half* __restrict__ Qh, const __half* __restrict__ Kh,
                    const __half* __restrict__ Vh, __half* __restrict__ O) {
  __shared__ __half Ks[2][AT_TK][KLD];
  __shared__ __half Vs[2][AT_TK][KLD];
  __shared__ unsigned Ps[AT_WARPS][16][20];

  const int b = blockIdx.z;
  const int h = blockIdx.y;
  const int r0 = blockIdx.x * AT_QB;
  const int kvh = h / REP_;
  const int warp = threadIdx.x >> 5;
  const int lane = threadIdx.x & 31;
  const int g = lane >> 2;
  const int tig = lane & 3;
  const int row0 = r0 + warp * AT_WQ;

  const uint32_t sKs = smem_u32(&Ks[0][0][0]);
  const uint32_t sVs = smem_u32(&Vs[0][0][0]);
  const uint32_t KVB = AT_TK * KLD * 2;  // bytes per buffer

  unsigned qa[8][4];
  {
    const __half* Qb = Qh + ((size_t)(b * L_ + row0) * H_ + h) * HD_;
#pragma unroll
    for (int s = 0; s < 8; s++) {
      const int k0 = s * 16 + 2 * tig;
      qa[s][0] = *(const unsigned*)(Qb + (size_t)g * D_ + k0);
      qa[s][1] = *(const unsigned*)(Qb + (size_t)(g + 8) * D_ + k0);
      qa[s][2] = *(const unsigned*)(Qb + (size_t)g * D_ + k0 + 8);
      qa[s][3] = *(const unsigned*)(Qb + (size_t)(g + 8) * D_ + k0 + 8);
    }
  }

  float m0v = -CUDART_INF_F, m1v = -CUDART_INF_F;
  float l0 = 0.f, l1 = 0.f;
  float oa[16][4];
#pragma unroll
  for (int j = 0; j < 16; j++)
#pragma unroll
    for (int q = 0; q < 4; q++) oa[j][q] = 0.f;

  uint32_t kdst[4];
  size_t ksrc[4];
#pragma unroll
  for (int i = 0; i < 4; i++) {
    int e = threadIdx.x + i * 128;
    int row = e >> 4, c = e & 15;
    kdst[i] = (uint32_t)(row * (KLD * 2) + c * 16);
    ksrc[i] = ((size_t)(b * L_ + row) * KV_ + kvh) * HD_ + c * 8;
  }

#define KV_LOADT(st, t0)                                                    \
  do {                                                                      \
    _Pragma("unroll")                                                       \
    for (int i = 0; i < 4; i++) {                                           \
      size_t sofs = ksrc[i] + (size_t)(t0) * (KV_ * HD_);                   \
      cp_async16(sKs + (st) * KVB + kdst[i], Kh + sofs);                    \
      cp_async16(sVs + (st) * KVB + kdst[i], Vh + sofs);                    \
    }                                                                       \
    asm volatile("cp.async.commit_group;" ::: "memory");                    \
  } while (0)

  const int tmax = row0 + AT_WQ - 1;
  const int t_end = r0 + AT_QB - 1;

  KV_LOADT(0, 0);

  for (int t0 = 0; t0 <= t_end; t0 += AT_TK) {
    const int buf = (t0 >> 5) & 1;
    if (t0 + AT_TK <= t_end) {
      KV_LOADT(buf ^ 1, t0 + AT_TK);
      asm volatile("cp.async.wait_group 1;" ::: "memory");
    } else {
      asm volatile("cp.async.wait_group 0;" ::: "memory");
    }
    __syncthreads();

    if (t0 <= tmax) {
      float sf[4][4];
#pragma unroll
      for (int j = 0; j < 4; j++)
#pragma unroll
        for (int q = 0; q < 4; q++) sf[j][q] = 0.f;

#pragma unroll
      for (int s = 0; s < 8; s++) {
        const int kb = s * 16 + 2 * tig;
        unsigned bk[4][2];
#pragma unroll
        for (int j = 0; j < 4; j++) {
          bk[j][0] = *(const unsigned*)&Ks[buf][j * 8 + g][kb];
          bk[j][1] = *(const unsigned*)&Ks[buf][j * 8 + g][kb + 8];
        }
#pragma unroll
        for (int j = 0; j < 4; j++) mma_f16(sf[j], qa[s], bk[j]);
      }

      if (t0 + AT_TK - 1 > row0) {
#pragma unroll
        for (int j = 0; j < 4; j++) {
          const int col = t0 + j * 8 + 2 * tig;
          if (col > row0 + g) sf[j][0] = -CUDART_INF_F;
          if (col + 1 > row0 + g) sf[j][1] = -CUDART_INF_F;
          if (col > row0 + g + 8) sf[j][2] = -CUDART_INF_F;
          if (col + 1 > row0 + g + 8) sf[j][3] = -CUDART_INF_F;
        }
      }

      float tm0 = sf[0][0], tm1 = sf[0][2];
#pragma unroll
      for (int j = 0; j < 4; j++) {
        tm0 = fmaxf(tm0, fmaxf(sf[j][0], sf[j][1]));
        tm1 = fmaxf(tm1, fmaxf(sf[j][2], sf[j][3]));
      }
      tm0 = fmaxf(tm0, __shfl_xor_sync(0xffffffffu, tm0, 1));
      tm0 = fmaxf(tm0, __shfl_xor_sync(0xffffffffu, tm0, 2));
      tm1 = fmaxf(tm1, __shfl_xor_sync(0xffffffffu, tm1, 1));
      tm1 = fmaxf(tm1, __shfl_xor_sync(0xffffffffu, tm1, 2));

      const float mn0 = fmaxf(m0v, tm0);
      const float mn1 = fmaxf(m1v, tm1);
      const float cr0 = __expf(m0v - mn0);
      const float cr1 = __expf(m1v - mn1);

      float ps0 = 0.f, ps1 = 0.f;
#pragma unroll
      for (int j = 0; j < 4; j++) {
        sf[j][0] = __expf(sf[j][0] - mn0);
        sf[j][1] = __expf(sf[j][1] - mn0);
        sf[j][2] = __expf(sf[j][2] - mn1);
        sf[j][3] = __expf(sf[j][3] - mn1);
        ps0 += sf[j][0] + sf[j][1];
        ps1 += sf[j][2] + sf[j][3];
      }
      ps0 += __shfl_xor_sync(0xffffffffu, ps0, 1);
      ps0 += __shfl_xor_sync(0xffffffffu, ps0, 2);
      ps1 += __shfl_xor_sync(0xffffffffu, ps1, 1);
      ps1 += __shfl_xor_sync(0xffffffffu, ps1, 2);

      l0 = l0 * cr0 + ps0;
      l1 = l1 * cr1 + ps1;
      m0v = mn0;
      m1v = mn1;

#pragma unroll
      for (int j2 = 0; j2 < 16; j2++) {
        oa[j2][0] *= cr0; oa[j2][1] *= cr0;
        oa[j2][2] *= cr1; oa[j2][3] *= cr1;
      }

#pragma unroll
      for (int j = 0; j < 4; j++) {
        __half2 p0 = __floats2half2_rn(sf[j][0], sf[j][1]);
        __half2 p1 = __floats2half2_rn(sf[j][2], sf[j][3]);
        Ps[warp][g][j * 4 + tig] = *(unsigned*)&p0;
        Ps[warp][g + 8][j * 4 + tig] = *(unsigned*)&p1;
      }
      __syncwarp();

#pragma unroll
      for (int s = 0; s < 2; s++) {
        unsigned pa[4];
        pa[0] = Ps[warp][g][s * 8 + tig];
        pa[1] = Ps[warp][g + 8][s * 8 + tig];
        pa[2] = Ps[warp][g][s * 8 + tig + 4];
        pa[3] = Ps[warp][g + 8][s * 8 + tig + 4];
        const uint32_t vrow =
            sVs + buf * KVB + (s * 16 + (lane & 15)) * (KLD * 2);
#pragma unroll
        for (int j2 = 0; j2 < 16; j2++) {
          unsigned bv[2];
          ldmx2t(bv[0], bv[1], vrow + j2 * 16);
          mma_f16(oa[j2], pa, bv);
        }
      }
    }
    __syncthreads();
  }

  const float inv0 = 1.0f / l0;
  const float inv1 = 1.0f / l1;
  __half* Ob = O + ((size_t)(b * L_ + row0) * H_ + h) * HD_;
#pragma unroll
  for (int j2 = 0; j2 < 16; j2++) {
    const int col = j2 * 8 + 2 * tig;
    *(__half2*)(Ob + (size_t)g * D_ + col) =
        __floats2half2_rn(oa[j2][0] * inv0, oa[j2][1] * inv0);
    *(__half2*)(Ob + (size_t)(g + 8) * D_ + col) =
        __floats2half2_rn(oa[j2][2] * inv1, oa[j2][3] * inv1);
  }
}

// ---------------------------------------------------------------------------
extern "C" void kernel_launch(void* const* d_in, const int* in_sizes, int n_in,
                              void* d_out, int out_size) {
  (void)in_sizes; (void)n_in; (void)out_size;
  const float* x  = (const float*)d_in[0];
  const float* wq = (const float*)d_in[1];
  const float* wk = (const float*)d_in[2];
  const float* wv = (const float*)d_in[3];
  const float* wo = (const float*)d_in[4];
  float* out = (float*)d_out;

  float *q, *k;
  __half *qh, *kh, *vh, *xh, *wqh, *wkh, *wvh, *woh, *aoh;
  cudaGetSymbolAddress((void**)&q, g_q);
  cudaGetSymbolAddress((void**)&k, g_k);
  cudaGetSymbolAddress((void**)&qh, g_qh);
  cudaGetSymbolAddress((void**)&kh, g_kh);
  cudaGetSymbolAddress((void**)&vh, g_vh);
  cudaGetSymbolAddress((void**)&xh, g_xh);
  cudaGetSymbolAddress((void**)&wqh, g_wqh);
  cudaGetSymbolAddress((void**)&wkh, g_wkh);
  cudaGetSymbolAddress((void**)&wvh, g_wvh);
  cudaGetSymbolAddress((void**)&woh, g_woh);
  cudaGetSymbolAddress((void**)&aoh, g_aoh);

  const int M = B_ * L_;  // 4096

  // fp16 conversion of GEMM operands
  {
    int n4;
    n4 = (B_ * L_ * D_) / 4;
    cvt_f16_kernel<<<(n4 + 255) / 256, 256>>>(x, xh, n4);
    n4 = (D_ * D_) / 4;
    cvt_f16_kernel<<<(n4 + 255) / 256, 256>>>(wq, wqh, n4);
    cvt_f16_kernel<<<(n4 + 255) / 256, 256>>>(wo, woh, n4);
    n4 = (KV_ * HD_ * D_) / 4;
    cvt_f16_kernel<<<(n4 + 255) / 256, 256>>>(wk, wkh, n4);
    cvt_f16_kernel<<<(n4 + 255) / 256, 256>>>(wv, wvh, n4);
  }

  // Q/K/V projections (fp16 mma + ldmatrix, 2-stage static smem)
  gemm_f16<float><<<dim3(D_ / FBN, M / FBM), 256>>>(xh, wqh, q, M, D_, D_);
  gemm_f16<float><<<dim3((KV_ * HD_) / FBN, M / FBM), 256>>>(xh, wkh, k, M,
                                                             KV_ * HD_, D_);
  gemm_f16<__half><<<dim3((KV_ * HD_) / FBN, M / FBM), 256>>>(xh, wvh, vh, M,
                                                              KV_ * HD_, D_);

  // RoPE: fp32 -> fp16, q gets softmax scale folded in
  const float scale = 0.088388347648318447f;  // 1/sqrt(128)
  int nq = B_ * L_ * H_ * (HD_ / 2);
  rope_h_kernel<<<nq / 256, 256>>>(q, qh, H_, nq, scale);
  int nk = B_ * L_ * KV_ * (HD_ / 2);
  rope_h_kernel<<<nk / 256, 256>>>(k, kh, KV_, nk, 1.0f);

  // causal attention (fp16 tensor cores)
  flash_attn_f16<<<dim3(L_ / AT_QB, H_, B_), 128>>>(qh, kh, vh, aoh);

  // output projection -> d_out
  gemm_f16<float><<<dim3(D_ / FBN, M / FBM), 256>>>(aoh, woh, out, M, D_, D_);
}

// round 8
// speedup vs baseline: 1.5534x; 1.0328x over previous
#include <cuda_runtime.h>
#include <cuda_fp16.h>
#include <math_constants.h>
#include <cstdint>

#define B_ 2
#define L_ 2048
#define D_ 2048
#define H_ 16
#define KV_ 4
#define HD_ 128
#define REP_ (H_ / KV_)

// Scratch (allocation-free rule: device globals)
__device__ float g_q[(size_t)B_ * L_ * D_];             // 32 MB (pre-rope q)
__device__ float g_k[(size_t)B_ * L_ * KV_ * HD_];      // 8 MB  (pre-rope k)
__device__ __half g_qh[(size_t)B_ * L_ * D_];           // 16 MB (roped q * scale)
__device__ __half g_kh[(size_t)B_ * L_ * KV_ * HD_];    // 4 MB  (roped k)
__device__ __half g_vh[(size_t)B_ * L_ * KV_ * HD_];    // 4 MB
__device__ __half g_xh[(size_t)B_ * L_ * D_];           // 16 MB
__device__ __half g_wqh[(size_t)D_ * D_];               // 8 MB
__device__ __half g_wkh[(size_t)KV_ * HD_ * D_];        // 2 MB
__device__ __half g_wvh[(size_t)KV_ * HD_ * D_];        // 2 MB
__device__ __half g_woh[(size_t)D_ * D_];               // 8 MB
__device__ __half g_aoh[(size_t)B_ * L_ * D_];          // 16 MB

// ---------------------------------------------------------------------------
// helpers
// ---------------------------------------------------------------------------
__device__ __forceinline__ void mma_f16(float c[4], const unsigned a[4],
                                        const unsigned b[2]) {
  asm volatile(
      "mma.sync.aligned.m16n8k16.row.col.f32.f16.f16.f32 "
      "{%0,%1,%2,%3}, {%4,%5,%6,%7}, {%8,%9}, {%0,%1,%2,%3};"
      : "+f"(c[0]), "+f"(c[1]), "+f"(c[2]), "+f"(c[3])
      : "r"(a[0]), "r"(a[1]), "r"(a[2]), "r"(a[3]), "r"(b[0]), "r"(b[1]));
}

__device__ __forceinline__ void ldmx4(unsigned r[4], uint32_t addr) {
  asm volatile(
      "ldmatrix.sync.aligned.m8n8.x4.shared.b16 {%0,%1,%2,%3}, [%4];"
      : "=r"(r[0]), "=r"(r[1]), "=r"(r[2]), "=r"(r[3]) : "r"(addr));
}

__device__ __forceinline__ void ldmx2t(unsigned& r0, unsigned& r1,
                                       uint32_t addr) {
  asm volatile(
      "ldmatrix.sync.aligned.m8n8.x2.trans.shared.b16 {%0,%1}, [%2];"
      : "=r"(r0), "=r"(r1) : "r"(addr));
}

__device__ __forceinline__ uint32_t smem_u32(const void* p) {
  uint32_t a;
  asm("{ .reg .u64 t; cvta.to.shared.u64 t, %1; cvt.u32.u64 %0, t; }"
      : "=r"(a) : "l"(p));
  return a;
}

__device__ __forceinline__ void cp_async16(uint32_t dst, const void* src) {
  asm volatile("cp.async.cg.shared.global [%0], [%1], 16;\n"
               :: "r"(dst), "l"(src) : "memory");
}

// ---------------------------------------------------------------------------
// fp16 tensor-core GEMM core (round-5/7 structure, unchanged inner loop):
// 128x128 CTA tile, BK=32, 256 threads (8 warps 2x4), warp tile 64x32,
// m16n8k16 + ldmatrix, 2-stage static-smem cp.async pipeline.
// Fused-QKV wrapper selects W/output per CTA (uniform branch; all tiles equal
// work). O-projection uses the same core with a single matrix.
// ---------------------------------------------------------------------------
#define FBM 128
#define FBN 128
#define FBK 32
#define FLD 40   // halfs per row (32 + 8 pad)

struct GemmOut {
  float* f;      // fp32 output (q, k, out)
  __half* h;     // fp16 output (v) — used when f == nullptr
};

__device__ __forceinline__ void gemm_core(
    const __half* __restrict__ Ab, const __half* __restrict__ Wb,
    float* __restrict__ Cf, __half* __restrict__ Ch,
    int N, int Kd, int bm, int bn,
    __half (*As)[FBM][FLD], __half (*Bs)[FBM][FLD]) {
  const int tid = threadIdx.x;
  const int warp = tid >> 5;
  const int lane = tid & 31;
  const int m0 = (warp >> 2) * 64;
  const int n0 = (warp & 3) * 32;

  const uint32_t sbA = smem_u32(&As[0][0][0]);
  const uint32_t sbB = smem_u32(&Bs[0][0][0]);
  const uint32_t BUFB = FBM * FLD * 2;

  const int r0c = tid >> 2, c0c = (tid & 3);
  const int r1c = (tid + 256) >> 2, c1c = ((tid + 256) & 3);
  const uint32_t d0 = (uint32_t)(r0c * FLD * 2 + c0c * 16);
  const uint32_t d1 = (uint32_t)(r1c * FLD * 2 + c1c * 16);
  const size_t s0 = (size_t)r0c * Kd + c0c * 8;
  const size_t s1 = (size_t)r1c * Kd + c1c * 8;

#define F16_LOAD(buf, k0)                                                   \
  do {                                                                      \
    cp_async16(sbA + (buf)*BUFB + d0, Ab + s0 + (k0));                      \
    cp_async16(sbA + (buf)*BUFB + d1, Ab + s1 + (k0));                      \
    cp_async16(sbB + (buf)*BUFB + d0, Wb + s0 + (k0));                      \
    cp_async16(sbB + (buf)*BUFB + d1, Wb + s1 + (k0));                      \
    asm volatile("cp.async.commit_group;" ::: "memory");                    \
  } while (0)

  const uint32_t a_off =
      (uint32_t)(((m0 + (lane & 15)) * FLD + ((lane >> 4) << 3)) * 2);
  const uint32_t b_off =
      (uint32_t)(((n0 + (lane & 7) + ((lane >> 4) & 1) * 8) * FLD +
                  ((lane >> 3) & 1) * 8) * 2);

  float acc[4][4][4];
#pragma unroll
  for (int i = 0; i < 4; i++)
#pragma unroll
    for (int j = 0; j < 4; j++)
#pragma unroll
      for (int q = 0; q < 4; q++) acc[i][j][q] = 0.f;

  const int nk = Kd / FBK;
  F16_LOAD(0, 0);

  for (int t = 0; t < nk; t++) {
    const int buf = t & 1;
    if (t + 1 < nk) {
      F16_LOAD(buf ^ 1, (t + 1) * FBK);
      asm volatile("cp.async.wait_group 1;" ::: "memory");
    } else {
      asm volatile("cp.async.wait_group 0;" ::: "memory");
    }
    __syncthreads();

    const uint32_t aB = sbA + buf * BUFB + a_off;
    const uint32_t bB = sbB + buf * BUFB + b_off;
#pragma unroll
    for (int ks = 0; ks < 2; ks++) {
      const uint32_t ksb = ks * 32;
      unsigned a[4][4], b[4][2];
#pragma unroll
      for (int i = 0; i < 4; i++) ldmx4(a[i], aB + i * (16 * FLD * 2) + ksb);
      {
        unsigned t4[4];
        ldmx4(t4, bB + ksb);
        b[0][0] = t4[0]; b[0][1] = t4[1]; b[1][0] = t4[2]; b[1][1] = t4[3];
        ldmx4(t4, bB + 16 * FLD * 2 + ksb);
        b[2][0] = t4[0]; b[2][1] = t4[1]; b[3][0] = t4[2]; b[3][1] = t4[3];
      }
#pragma unroll
      for (int i = 0; i < 4; i++)
#pragma unroll
        for (int j = 0; j < 4; j++) mma_f16(acc[i][j], a[i], b[j]);
    }
    __syncthreads();
  }

  const int g = lane >> 2;
  const int tig = lane & 3;
  if (Cf) {
#pragma unroll
    for (int i = 0; i < 4; i++)
#pragma unroll
      for (int j = 0; j < 4; j++) {
        const size_t row1 = (size_t)(bm + m0 + i * 16 + g);
        const int col = bn + n0 + j * 8 + tig * 2;
        *(float2*)(Cf + row1 * N + col) = make_float2(acc[i][j][0], acc[i][j][1]);
        *(float2*)(Cf + (row1 + 8) * N + col) =
            make_float2(acc[i][j][2], acc[i][j][3]);
      }
  } else {
#pragma unroll
    for (int i = 0; i < 4; i++)
#pragma unroll
      for (int j = 0; j < 4; j++) {
        const size_t row1 = (size_t)(bm + m0 + i * 16 + g);
        const int col = bn + n0 + j * 8 + tig * 2;
        *(__half2*)(Ch + row1 * N + col) =
            __floats2half2_rn(acc[i][j][0], acc[i][j][1]);
        *(__half2*)(Ch + (row1 + 8) * N + col) =
            __floats2half2_rn(acc[i][j][2], acc[i][j][3]);
      }
  }
}

// Fused QKV projection: blockIdx.x 0..15 -> Q tile, 16..19 -> K, 20..23 -> V.
__global__ __launch_bounds__(256, 2)
void gemm_qkv(const __half* __restrict__ xh, const __half* __restrict__ wqh,
              const __half* __restrict__ wkh, const __half* __restrict__ wvh,
              float* __restrict__ q, float* __restrict__ k,
              __half* __restrict__ vh, int M, int Kd) {
  __shared__ __half As[2][FBM][FLD];
  __shared__ __half Bs[2][FBM][FLD];
  const int bxx = blockIdx.x;
  const int bm = blockIdx.y * FBM;

  const __half* W;
  float* Cf = nullptr;
  __half* Ch = nullptr;
  int N, bn;
  if (bxx < 16) {
    W = wqh; Cf = q; N = D_; bn = bxx * FBN;
  } else if (bxx < 20) {
    W = wkh; Cf = k; N = KV_ * HD_; bn = (bxx - 16) * FBN;
  } else {
    W = wvh; Ch = vh; N = KV_ * HD_; bn = (bxx - 20) * FBN;
  }
  gemm_core(xh + (size_t)bm * Kd, W + (size_t)bn * Kd, Cf, Ch, N, Kd, bm, bn,
            As, Bs);
}

// Single GEMM (O projection): C fp32.
__global__ __launch_bounds__(256, 2)
void gemm_single(const __half* __restrict__ A, const __half* __restrict__ W,
                 float* __restrict__ C, int M, int N, int Kd) {
  __shared__ __half As[2][FBM][FLD];
  __shared__ __half Bs[2][FBM][FLD];
  const int bm = blockIdx.y * FBM;
  const int bn = blockIdx.x * FBN;
  gemm_core(A + (size_t)bm * Kd, W + (size_t)bn * Kd, C, nullptr, N, Kd, bm,
            bn, As, Bs);
}

// ---------------------------------------------------------------------------
// merged fp32 -> fp16 convert over 5 segments (x, wq, wo, wk, wv)
// ---------------------------------------------------------------------------
__global__ void cvt_all_kernel(const float* s0, __half* d0, int n0,
                               const float* s1, __half* d1, int n1,
                               const float* s2, __half* d2, int n2,
                               const float* s3, __half* d3, int n3,
                               const float* s4, __half* d4, int n4t) {
  int i = blockIdx.x * blockDim.x + threadIdx.x;
  const float* s;
  __half* d;
  if (i < n0) { s = s0; d = d0; }
  else if ((i -= n0) < n1) { s = s1; d = d1; }
  else if ((i -= n1) < n2) { s = s2; d = d2; }
  else if ((i -= n2) < n3) { s = s3; d = d3; }
  else if ((i -= n3) < n4t) { s = s4; d = d4; }
  else return;
  float4 v = ((const float4*)s)[i];
  __half2 lo = __floats2half2_rn(v.x, v.y);
  __half2 hi = __floats2half2_rn(v.z, v.w);
  ((uint2*)d)[i] = make_uint2(*(unsigned*)&lo, *(unsigned*)&hi);
}

// ---------------------------------------------------------------------------
// RoPE: fp32 in -> fp16 out, optional scale folded in.
// ---------------------------------------------------------------------------
__global__ void rope_h_kernel(const float* __restrict__ in,
                              __half* __restrict__ out, int nh, int total,
                              float sc) {
  int idx = blockIdx.x * blockDim.x + threadIdx.x;
  if (idx >= total) return;
  int i = idx & (HD_ / 2 - 1);
  int t = idx >> 6;
  int h = t % nh;
  int bl = t / nh;
  int pos = bl & (L_ - 1);
  float inv_freq = expf(-(float)i * (2.0f / HD_) * 9.210340371976184f);
  float ang = (float)pos * inv_freq;
  float s, c;
  sincosf(ang, &s, &c);
  size_t base = ((size_t)bl * nh + h) * HD_ + 2 * i;
  float x1 = in[base], x2 = in[base + 1];
  *(__half2*)(out + base) =
      __floats2half2_rn((x1 * c - x2 * s) * sc, (x1 * s + x2 * c) * sc);
}

// ---------------------------------------------------------------------------
// fp16 tensor-core causal flash attention (round-7 math, block order reversed
// so heavy diagonal blocks launch first).
// ---------------------------------------------------------------------------
#define AT_TK 32
#define AT_WQ 16
#define AT_WARPS 4
#define AT_QB (AT_WQ * AT_WARPS)   // 64
#define KLD 136                    // halfs per K/V smem row (128 + 8)

__global__ __launch_bounds__(128, 3)
void flash_attn_f16(const __half* __restrict__ Qh, const __half* __restrict__ Kh,
                    const __half* __restrict__ Vh, __half* __restrict__ O) {
  __shared__ __half Ks[2][AT_TK][KLD];
  __shared__ __half Vs[2][AT_TK][KLD];
  __shared__ unsigned Ps[AT_WARPS][16][20];

  const int b = blockIdx.z;
  const int h = blockIdx.y;
  const int r0 = (gridDim.x - 1 - blockIdx.x) * AT_QB;  // heavy blocks first
  const int kvh = h / REP_;
  const int warp = threadIdx.x >> 5;
  const int lane = threadIdx.x & 31;
  const int g = lane >> 2;
  const int tig = lane & 3;
  const int row0 = r0 + warp * AT_WQ;

  const uint32_t sKs = smem_u32(&Ks[0][0][0]);
  const uint32_t sVs = smem_u32(&Vs[0][0][0]);
  const uint32_t KVB = AT_TK * KLD * 2;

  unsigned qa[8][4];
  {
    const __half* Qb = Qh + ((size_t)(b * L_ + row0) * H_ + h) * HD_;
#pragma unroll
    for (int s = 0; s < 8; s++) {
      const int k0 = s * 16 + 2 * tig;
      qa[s][0] = *(const unsigned*)(Qb + (size_t)g * D_ + k0);
      qa[s][1] = *(const unsigned*)(Qb + (size_t)(g + 8) * D_ + k0);
      qa[s][2] = *(const unsigned*)(Qb + (size_t)g * D_ + k0 + 8);
      qa[s][3] = *(const unsigned*)(Qb + (size_t)(g + 8) * D_ + k0 + 8);
    }
  }

  float m0v = -CUDART_INF_F, m1v = -CUDART_INF_F;
  float l0 = 0.f, l1 = 0.f;
  float oa[16][4];
#pragma unroll
  for (int j = 0; j < 16; j++)
#pragma unroll
    for (int q = 0; q < 4; q++) oa[j][q] = 0.f;

  uint32_t kdst[4];
  size_t ksrc[4];
#pragma unroll
  for (int i = 0; i < 4; i++) {
    int e = threadIdx.x + i * 128;
    int row = e >> 4, c = e & 15;
    kdst[i] = (uint32_t)(row * (KLD * 2) + c * 16);
    ksrc[i] = ((size_t)(b * L_ + row) * KV_ + kvh) * HD_ + c * 8;
  }

#define KV_LOADT(st, t0)                                                    \
  do {                                                                      \
    _Pragma("unroll")                                                       \
    for (int i = 0; i < 4; i++) {                                           \
      size_t sofs = ksrc[i] + (size_t)(t0) * (KV_ * HD_);                   \
      cp_async16(sKs + (st) * KVB + kdst[i], Kh + sofs);                    \
      cp_async16(sVs + (st) * KVB + kdst[i], Vh + sofs);                    \
    }                                                                       \
    asm volatile("cp.async.commit_group;" ::: "memory");                    \
  } while (0)

  const int tmax = row0 + AT_WQ - 1;
  const int t_end = r0 + AT_QB - 1;

  KV_LOADT(0, 0);

  for (int t0 = 0; t0 <= t_end; t0 += AT_TK) {
    const int buf = (t0 >> 5) & 1;
    if (t0 + AT_TK <= t_end) {
      KV_LOADT(buf ^ 1, t0 + AT_TK);
      asm volatile("cp.async.wait_group 1;" ::: "memory");
    } else {
      asm volatile("cp.async.wait_group 0;" ::: "memory");
    }
    __syncthreads();

    if (t0 <= tmax) {
      float sf[4][4];
#pragma unroll
      for (int j = 0; j < 4; j++)
#pragma unroll
        for (int q = 0; q < 4; q++) sf[j][q] = 0.f;

#pragma unroll
      for (int s = 0; s < 8; s++) {
        const int kb = s * 16 + 2 * tig;
        unsigned bk[4][2];
#pragma unroll
        for (int j = 0; j < 4; j++) {
          bk[j][0] = *(const unsigned*)&Ks[buf][j * 8 + g][kb];
          bk[j][1] = *(const unsigned*)&Ks[buf][j * 8 + g][kb + 8];
        }
#pragma unroll
        for (int j = 0; j < 4; j++) mma_f16(sf[j], qa[s], bk[j]);
      }

      if (t0 + AT_TK - 1 > row0) {
#pragma unroll
        for (int j = 0; j < 4; j++) {
          const int col = t0 + j * 8 + 2 * tig;
          if (col > row0 + g) sf[j][0] = -CUDART_INF_F;
          if (col + 1 > row0 + g) sf[j][1] = -CUDART_INF_F;
          if (col > row0 + g + 8) sf[j][2] = -CUDART_INF_F;
          if (col + 1 > row0 + g + 8) sf[j][3] = -CUDART_INF_F;
        }
      }

      float tm0 = sf[0][0], tm1 = sf[0][2];
#pragma unroll
      for (int j = 0; j < 4; j++) {
        tm0 = fmaxf(tm0, fmaxf(sf[j][0], sf[j][1]));
        tm1 = fmaxf(tm1, fmaxf(sf[j][2], sf[j][3]));
      }
      tm0 = fmaxf(tm0, __shfl_xor_sync(0xffffffffu, tm0, 1));
      tm0 = fmaxf(tm0, __shfl_xor_sync(0xffffffffu, tm0, 2));
      tm1 = fmaxf(tm1, __shfl_xor_sync(0xffffffffu, tm1, 1));
      tm1 = fmaxf(tm1, __shfl_xor_sync(0xffffffffu, tm1, 2));

      const float mn0 = fmaxf(m0v, tm0);
      const float mn1 = fmaxf(m1v, tm1);
      const float cr0 = __expf(m0v - mn0);
      const float cr1 = __expf(m1v - mn1);

      float ps0 = 0.f, ps1 = 0.f;
#pragma unroll
      for (int j = 0; j < 4; j++) {
        sf[j][0] = __expf(sf[j][0] - mn0);
        sf[j][1] = __expf(sf[j][1] - mn0);
        sf[j][2] = __expf(sf[j][2] - mn1);
        sf[j][3] = __expf(sf[j][3] - mn1);
        ps0 += sf[j][0] + sf[j][1];
        ps1 += sf[j][2] + sf[j][3];
      }
      ps0 += __shfl_xor_sync(0xffffffffu, ps0, 1);
      ps0 += __shfl_xor_sync(0xffffffffu, ps0, 2);
      ps1 += __shfl_xor_sync(0xffffffffu, ps1, 1);
      ps1 += __shfl_xor_sync(0xffffffffu, ps1, 2);

      l0 = l0 * cr0 + ps0;
      l1 = l1 * cr1 + ps1;
      m0v = mn0;
      m1v = mn1;

#pragma unroll
      for (int j2 = 0; j2 < 16; j2++) {
        oa[j2][0] *= cr0; oa[j2][1] *= cr0;
        oa[j2][2] *= cr1; oa[j2][3] *= cr1;
      }

#pragma unroll
      for (int j = 0; j < 4; j++) {
        __half2 p0 = __floats2half2_rn(sf[j][0], sf[j][1]);
        __half2 p1 = __floats2half2_rn(sf[j][2], sf[j][3]);
        Ps[warp][g][j * 4 + tig] = *(unsigned*)&p0;
        Ps[warp][g + 8][j * 4 + tig] = *(unsigned*)&p1;
      }
      __syncwarp();

#pragma unroll
      for (int s = 0; s < 2; s++) {
        unsigned pa[4];
        pa[0] = Ps[warp][g][s * 8 + tig];
        pa[1] = Ps[warp][g + 8][s * 8 + tig];
        pa[2] = Ps[warp][g][s * 8 + tig + 4];
        pa[3] = Ps[warp][g + 8][s * 8 + tig + 4];
        const uint32_t vrow =
            sVs + buf * KVB + (s * 16 + (lane & 15)) * (KLD * 2);
#pragma unroll
        for (int j2 = 0; j2 < 16; j2++) {
          unsigned bv[2];
          ldmx2t(bv[0], bv[1], vrow + j2 * 16);
          mma_f16(oa[j2], pa, bv);
        }
      }
    }
    __syncthreads();
  }

  const float inv0 = 1.0f / l0;
  const float inv1 = 1.0f / l1;
  __half* Ob = O + ((size_t)(b * L_ + row0) * H_ + h) * HD_;
#pragma unroll
  for (int j2 = 0; j2 < 16; j2++) {
    const int col = j2 * 8 + 2 * tig;
    *(__half2*)(Ob + (size_t)g * D_ + col) =
        __floats2half2_rn(oa[j2][0] * inv0, oa[j2][1] * inv0);
    *(__half2*)(Ob + (size_t)(g + 8) * D_ + col) =
        __floats2half2_rn(oa[j2][2] * inv1, oa[j2][3] * inv1);
  }
}

// ---------------------------------------------------------------------------
extern "C" void kernel_launch(void* const* d_in, const int* in_sizes, int n_in,
                              void* d_out, int out_size) {
  (void)in_sizes; (void)n_in; (void)out_size;
  const float* x  = (const float*)d_in[0];
  const float* wq = (const float*)d_in[1];
  const float* wk = (const float*)d_in[2];
  const float* wv = (const float*)d_in[3];
  const float* wo = (const float*)d_in[4];
  float* out = (float*)d_out;

  float *q, *k;
  __half *qh, *kh, *vh, *xh, *wqh, *wkh, *wvh, *woh, *aoh;
  cudaGetSymbolAddress((void**)&q, g_q);
  cudaGetSymbolAddress((void**)&k, g_k);
  cudaGetSymbolAddress((void**)&qh, g_qh);
  cudaGetSymbolAddress((void**)&kh, g_kh);
  cudaGetSymbolAddress((void**)&vh, g_vh);
  cudaGetSymbolAddress((void**)&xh, g_xh);
  cudaGetSymbolAddress((void**)&wqh, g_wqh);
  cudaGetSymbolAddress((void**)&wkh, g_wkh);
  cudaGetSymbolAddress((void**)&wvh, g_wvh);
  cudaGetSymbolAddress((void**)&woh, g_woh);
  cudaGetSymbolAddress((void**)&aoh, g_aoh);

  const int M = B_ * L_;  // 4096

  // merged fp16 conversion of all GEMM operands
  {
    const int nx = (B_ * L_ * D_) / 4;
    const int nw = (D_ * D_) / 4;
    const int nkv = (KV_ * HD_ * D_) / 4;
    const int ntot = nx + 2 * nw + 2 * nkv;
    cvt_all_kernel<<<(ntot + 255) / 256, 256>>>(x, xh, nx, wq, wqh, nw, wo,
                                                woh, nw, wk, wkh, nkv, wv,
                                                wvh, nkv);
  }

  // Fused Q/K/V projections: one launch, 24x32 = 768 uniform tiles
  gemm_qkv<<<dim3(24, M / FBM), 256>>>(xh, wqh, wkh, wvh, q, k, vh, M, D_);

  // RoPE: fp32 -> fp16, q gets softmax scale folded in
  const float scale = 0.088388347648318447f;  // 1/sqrt(128)
  int nq = B_ * L_ * H_ * (HD_ / 2);
  rope_h_kernel<<<nq / 256, 256>>>(q, qh, H_, nq, scale);
  int nk = B_ * L_ * KV_ * (HD_ / 2);
  rope_h_kernel<<<nk / 256, 256>>>(k, kh, KV_, nk, 1.0f);

  // causal attention (fp16 tensor cores), heavy blocks first
  flash_attn_f16<<<dim3(L_ / AT_QB, H_, B_), 128>>>(qh, kh, vh, aoh);

  // output projection -> d_out
  gemm_single<<<dim3(D_ / FBN, M / FBM), 256>>>(aoh, woh, out, M, D_, D_);
}

// round 9
// speedup vs baseline: 1.6233x; 1.0450x over previous
#include <cuda_runtime.h>
#include <cuda_fp16.h>
#include <math_constants.h>
#include <cstdint>

#define B_ 2
#define L_ 2048
#define D_ 2048
#define H_ 16
#define KV_ 4
#define HD_ 128
#define REP_ (H_ / KV_)

// Scratch (allocation-free rule: device globals)
__device__ __half g_qh[(size_t)B_ * L_ * D_];           // 16 MB (roped q * scale)
__device__ __half g_kh[(size_t)B_ * L_ * KV_ * HD_];    // 4 MB  (roped k)
__device__ __half g_vh[(size_t)B_ * L_ * KV_ * HD_];    // 4 MB
__device__ __half g_xh[(size_t)B_ * L_ * D_];           // 16 MB
__device__ __half g_wqh[(size_t)D_ * D_];               // 8 MB
__device__ __half g_wkh[(size_t)KV_ * HD_ * D_];        // 2 MB
__device__ __half g_wvh[(size_t)KV_ * HD_ * D_];        // 2 MB
__device__ __half g_woh[(size_t)D_ * D_];               // 8 MB
__device__ __half g_aoh[(size_t)B_ * L_ * D_];          // 16 MB

// ---------------------------------------------------------------------------
// helpers
// ---------------------------------------------------------------------------
__device__ __forceinline__ void mma_f16(float c[4], const unsigned a[4],
                                        const unsigned b[2]) {
  asm volatile(
      "mma.sync.aligned.m16n8k16.row.col.f32.f16.f16.f32 "
      "{%0,%1,%2,%3}, {%4,%5,%6,%7}, {%8,%9}, {%0,%1,%2,%3};"
      : "+f"(c[0]), "+f"(c[1]), "+f"(c[2]), "+f"(c[3])
      : "r"(a[0]), "r"(a[1]), "r"(a[2]), "r"(a[3]), "r"(b[0]), "r"(b[1]));
}

__device__ __forceinline__ void ldmx4(unsigned r[4], uint32_t addr) {
  asm volatile(
      "ldmatrix.sync.aligned.m8n8.x4.shared.b16 {%0,%1,%2,%3}, [%4];"
      : "=r"(r[0]), "=r"(r[1]), "=r"(r[2]), "=r"(r[3]) : "r"(addr));
}

__device__ __forceinline__ void ldmx2t(unsigned& r0, unsigned& r1,
                                       uint32_t addr) {
  asm volatile(
      "ldmatrix.sync.aligned.m8n8.x2.trans.shared.b16 {%0,%1}, [%2];"
      : "=r"(r0), "=r"(r1) : "r"(addr));
}

__device__ __forceinline__ uint32_t smem_u32(const void* p) {
  uint32_t a;
  asm("{ .reg .u64 t; cvta.to.shared.u64 t, %1; cvt.u32.u64 %0, t; }"
      : "=r"(a) : "l"(p));
  return a;
}

__device__ __forceinline__ void cp_async16(uint32_t dst, const void* src) {
  asm volatile("cp.async.cg.shared.global [%0], [%1], 16;\n"
               :: "r"(dst), "l"(src) : "memory");
}

// ---------------------------------------------------------------------------
// fp16 tensor-core GEMM core (round-7 inner loop, UNCHANGED):
// 128x128 CTA tile, BK=32, 256 threads (8 warps 2x4), warp tile 64x32,
// m16n8k16 + ldmatrix, 2-stage static-smem cp.async pipeline.
// Epilogue modes: 0 = fp32 C; 1 = fp16 C; 2 = fp16 C with fused RoPE*scale
// (valid because each 128-col tile is exactly one head and each thread holds
// adjacent even/odd column pairs = RoPE rotation pairs).
// ---------------------------------------------------------------------------
#define FBM 128
#define FBN 128
#define FBK 32
#define FLD 40   // halfs per row (32 + 8 pad)

__device__ __forceinline__ void gemm_core(
    const __half* __restrict__ Ab, const __half* __restrict__ Wb,
    float* __restrict__ Cf, __half* __restrict__ Ch,
    int N, int Kd, int bm, int bn, int mode, float rscale,
    __half (*As)[FBM][FLD], __half (*Bs)[FBM][FLD]) {
  const int tid = threadIdx.x;
  const int warp = tid >> 5;
  const int lane = tid & 31;
  const int m0 = (warp >> 2) * 64;
  const int n0 = (warp & 3) * 32;

  const uint32_t sbA = smem_u32(&As[0][0][0]);
  const uint32_t sbB = smem_u32(&Bs[0][0][0]);
  const uint32_t BUFB = FBM * FLD * 2;

  const int r0c = tid >> 2, c0c = (tid & 3);
  const int r1c = (tid + 256) >> 2, c1c = ((tid + 256) & 3);
  const uint32_t d0 = (uint32_t)(r0c * FLD * 2 + c0c * 16);
  const uint32_t d1 = (uint32_t)(r1c * FLD * 2 + c1c * 16);
  const size_t s0 = (size_t)r0c * Kd + c0c * 8;
  const size_t s1 = (size_t)r1c * Kd + c1c * 8;

#define F16_LOAD(buf, k0)                                                   \
  do {                                                                      \
    cp_async16(sbA + (buf)*BUFB + d0, Ab + s0 + (k0));                      \
    cp_async16(sbA + (buf)*BUFB + d1, Ab + s1 + (k0));                      \
    cp_async16(sbB + (buf)*BUFB + d0, Wb + s0 + (k0));                      \
    cp_async16(sbB + (buf)*BUFB + d1, Wb + s1 + (k0));                      \
    asm volatile("cp.async.commit_group;" ::: "memory");                    \
  } while (0)

  const uint32_t a_off =
      (uint32_t)(((m0 + (lane & 15)) * FLD + ((lane >> 4) << 3)) * 2);
  const uint32_t b_off =
      (uint32_t)(((n0 + (lane & 7) + ((lane >> 4) & 1) * 8) * FLD +
                  ((lane >> 3) & 1) * 8) * 2);

  float acc[4][4][4];
#pragma unroll
  for (int i = 0; i < 4; i++)
#pragma unroll
    for (int j = 0; j < 4; j++)
#pragma unroll
      for (int q = 0; q < 4; q++) acc[i][j][q] = 0.f;

  const int nk = Kd / FBK;
  F16_LOAD(0, 0);

  for (int t = 0; t < nk; t++) {
    const int buf = t & 1;
    if (t + 1 < nk) {
      F16_LOAD(buf ^ 1, (t + 1) * FBK);
      asm volatile("cp.async.wait_group 1;" ::: "memory");
    } else {
      asm volatile("cp.async.wait_group 0;" ::: "memory");
    }
    __syncthreads();

    const uint32_t aB = sbA + buf * BUFB + a_off;
    const uint32_t bB = sbB + buf * BUFB + b_off;
#pragma unroll
    for (int ks = 0; ks < 2; ks++) {
      const uint32_t ksb = ks * 32;
      unsigned a[4][4], b[4][2];
#pragma unroll
      for (int i = 0; i < 4; i++) ldmx4(a[i], aB + i * (16 * FLD * 2) + ksb);
      {
        unsigned t4[4];
        ldmx4(t4, bB + ksb);
        b[0][0] = t4[0]; b[0][1] = t4[1]; b[1][0] = t4[2]; b[1][1] = t4[3];
        ldmx4(t4, bB + 16 * FLD * 2 + ksb);
        b[2][0] = t4[0]; b[2][1] = t4[1]; b[3][0] = t4[2]; b[3][1] = t4[3];
      }
#pragma unroll
      for (int i = 0; i < 4; i++)
#pragma unroll
        for (int j = 0; j < 4; j++) mma_f16(acc[i][j], a[i], b[j]);
    }
    __syncthreads();
  }

  const int g = lane >> 2;
  const int tig = lane & 3;
  if (mode == 0) {
#pragma unroll
    for (int i = 0; i < 4; i++)
#pragma unroll
      for (int j = 0; j < 4; j++) {
        const size_t row1 = (size_t)(bm + m0 + i * 16 + g);
        const int col = bn + n0 + j * 8 + tig * 2;
        *(float2*)(Cf + row1 * N + col) = make_float2(acc[i][j][0], acc[i][j][1]);
        *(float2*)(Cf + (row1 + 8) * N + col) =
            make_float2(acc[i][j][2], acc[i][j][3]);
      }
  } else if (mode == 1) {
#pragma unroll
    for (int i = 0; i < 4; i++)
#pragma unroll
      for (int j = 0; j < 4; j++) {
        const size_t row1 = (size_t)(bm + m0 + i * 16 + g);
        const int col = bn + n0 + j * 8 + tig * 2;
        *(__half2*)(Ch + row1 * N + col) =
            __floats2half2_rn(acc[i][j][0], acc[i][j][1]);
        *(__half2*)(Ch + (row1 + 8) * N + col) =
            __floats2half2_rn(acc[i][j][2], acc[i][j][3]);
      }
  } else {
    // mode 2: fused RoPE (interleaved-pair) + scale, fp16 out
    float invf[4];
#pragma unroll
    for (int j = 0; j < 4; j++) {
      const int p = ((n0 + j * 8 + tig * 2) & (HD_ - 1)) >> 1;
      invf[j] = expf(-(float)p * (2.0f / HD_) * 9.210340371976184f);
    }
#pragma unroll
    for (int i = 0; i < 4; i++) {
      const int r1 = bm + m0 + i * 16 + g;
      const float pos1 = (float)(r1 & (L_ - 1));
      const float pos2 = (float)((r1 + 8) & (L_ - 1));
#pragma unroll
      for (int j = 0; j < 4; j++) {
        const int col = bn + n0 + j * 8 + tig * 2;
        float s1, c1, s2, c2;
        sincosf(pos1 * invf[j], &s1, &c1);
        sincosf(pos2 * invf[j], &s2, &c2);
        const float x1 = acc[i][j][0], x2 = acc[i][j][1];
        const float y1 = acc[i][j][2], y2 = acc[i][j][3];
        *(__half2*)(Ch + (size_t)r1 * N + col) = __floats2half2_rn(
            (x1 * c1 - x2 * s1) * rscale, (x1 * s1 + x2 * c1) * rscale);
        *(__half2*)(Ch + (size_t)(r1 + 8) * N + col) = __floats2half2_rn(
            (y1 * c2 - y2 * s2) * rscale, (y1 * s2 + y2 * c2) * rscale);
      }
    }
  }
}

// Fused QKV projection with fused RoPE epilogues:
// blockIdx.x 0..15 -> Q tile (rope*scale), 16..19 -> K (rope), 20..23 -> V.
__global__ __launch_bounds__(256, 2)
void gemm_qkv(const __half* __restrict__ xh, const __half* __restrict__ wqh,
              const __half* __restrict__ wkh, const __half* __restrict__ wvh,
              __half* __restrict__ qh, __half* __restrict__ kh,
              __half* __restrict__ vh, int M, int Kd) {
  __shared__ __half As[2][FBM][FLD];
  __shared__ __half Bs[2][FBM][FLD];
  const int bxx = blockIdx.x;
  const int bm = blockIdx.y * FBM;

  const __half* W;
  __half* Ch;
  int N, bn, mode;
  float rscale;
  if (bxx < 16) {
    W = wqh; Ch = qh; N = D_; bn = bxx * FBN; mode = 2;
    rscale = 0.088388347648318447f;  // 1/sqrt(128)
  } else if (bxx < 20) {
    W = wkh; Ch = kh; N = KV_ * HD_; bn = (bxx - 16) * FBN; mode = 2;
    rscale = 1.0f;
  } else {
    W = wvh; Ch = vh; N = KV_ * HD_; bn = (bxx - 20) * FBN; mode = 1;
    rscale = 1.0f;
  }
  gemm_core(xh + (size_t)bm * Kd, W + (size_t)bn * Kd, nullptr, Ch, N, Kd, bm,
            bn, mode, rscale, As, Bs);
}

// Single GEMM (O projection): C fp32.
__global__ __launch_bounds__(256, 2)
void gemm_single(const __half* __restrict__ A, const __half* __restrict__ W,
                 float* __restrict__ C, int M, int N, int Kd) {
  __shared__ __half As[2][FBM][FLD];
  __shared__ __half Bs[2][FBM][FLD];
  const int bm = blockIdx.y * FBM;
  const int bn = blockIdx.x * FBN;
  gemm_core(A + (size_t)bm * Kd, W + (size_t)bn * Kd, C, nullptr, N, Kd, bm,
            bn, 0, 1.0f, As, Bs);
}

// ---------------------------------------------------------------------------
// merged fp32 -> fp16 convert over 5 segments (x, wq, wo, wk, wv)
// ---------------------------------------------------------------------------
__global__ void cvt_all_kernel(const float* s0, __half* d0, int n0,
                               const float* s1, __half* d1, int n1,
                               const float* s2, __half* d2, int n2,
                               const float* s3, __half* d3, int n3,
                               const float* s4, __half* d4, int n4t) {
  int i = blockIdx.x * blockDim.x + threadIdx.x;
  const float* s;
  __half* d;
  if (i < n0) { s = s0; d = d0; }
  else if ((i -= n0) < n1) { s = s1; d = d1; }
  else if ((i -= n1) < n2) { s = s2; d = d2; }
  else if ((i -= n2) < n3) { s = s3; d = d3; }
  else if ((i -= n3) < n4t) { s = s4; d = d4; }
  else return;
  float4 v = ((const float4*)s)[i];
  __half2 lo = __floats2half2_rn(v.x, v.y);
  __half2 hi = __floats2half2_rn(v.z, v.w);
  ((uint2*)d)[i] = make_uint2(*(unsigned*)&lo, *(unsigned*)&hi);
}

// ---------------------------------------------------------------------------
// fp16 tensor-core causal flash attention (unchanged from round 8).
// ---------------------------------------------------------------------------
#define AT_TK 32
#define AT_WQ 16
#define AT_WARPS 4
#define AT_QB (AT_WQ * AT_WARPS)   // 64
#define KLD 136                    // halfs per K/V smem row (128 + 8)

__global__ __launch_bounds__(128, 3)
void flash_attn_f16(const __half* __restrict__ Qh, const __half* __restrict__ Kh,
                    const __half* __restrict__ Vh, __half* __restrict__ O) {
  __shared__ __half Ks[2][AT_TK][KLD];
  __shared__ __half Vs[2][AT_TK][KLD];
  __shared__ unsigned Ps[AT_WARPS][16][20];

  const int b = blockIdx.z;
  const int h = blockIdx.y;
  const int r0 = (gridDim.x - 1 - blockIdx.x) * AT_QB;  // heavy blocks first
  const int kvh = h / REP_;
  const int warp = threadIdx.x >> 5;
  const int lane = threadIdx.x & 31;
  const int g = lane >> 2;
  const int tig = lane & 3;
  const int row0 = r0 + warp * AT_WQ;

  const uint32_t sKs = smem_u32(&Ks[0][0][0]);
  const uint32_t sVs = smem_u32(&Vs[0][0][0]);
  const uint32_t KVB = AT_TK * KLD * 2;

  unsigned qa[8][4];
  {
    const __half* Qb = Qh + ((size_t)(b * L_ + row0) * H_ + h) * HD_;
#pragma unroll
    for (int s = 0; s < 8; s++) {
      const int k0 = s * 16 + 2 * tig;
      qa[s][0] = *(const unsigned*)(Qb + (size_t)g * D_ + k0);
      qa[s][1] = *(const unsigned*)(Qb + (size_t)(g + 8) * D_ + k0);
      qa[s][2] = *(const unsigned*)(Qb + (size_t)g * D_ + k0 + 8);
      qa[s][3] = *(const unsigned*)(Qb + (size_t)(g + 8) * D_ + k0 + 8);
    }
  }

  float m0v = -CUDART_INF_F, m1v = -CUDART_INF_F;
  float l0 = 0.f, l1 = 0.f;
  float oa[16][4];
#pragma unroll
  for (int j = 0; j < 16; j++)
#pragma unroll
    for (int q = 0; q < 4; q++) oa[j][q] = 0.f;

  uint32_t kdst[4];
  size_t ksrc[4];
#pragma unroll
  for (int i = 0; i < 4; i++) {
    int e = threadIdx.x + i * 128;
    int row = e >> 4, c = e & 15;
    kdst[i] = (uint32_t)(row * (KLD * 2) + c * 16);
    ksrc[i] = ((size_t)(b * L_ + row) * KV_ + kvh) * HD_ + c * 8;
  }

#define KV_LOADT(st, t0)                                                    \
  do {                                                                      \
    _Pragma("unroll")                                                       \
    for (int i = 0; i < 4; i++) {                                           \
      size_t sofs = ksrc[i] + (size_t)(t0) * (KV_ * HD_);                   \
      cp_async16(sKs + (st) * KVB + kdst[i], Kh + sofs);                    \
      cp_async16(sVs + (st) * KVB + kdst[i], Vh + sofs);                    \
    }                                                                       \
    asm volatile("cp.async.commit_group;" ::: "memory");                    \
  } while (0)

  const int tmax = row0 + AT_WQ - 1;
  const int t_end = r0 + AT_QB - 1;

  KV_LOADT(0, 0);

  for (int t0 = 0; t0 <= t_end; t0 += AT_TK) {
    const int buf = (t0 >> 5) & 1;
    if (t0 + AT_TK <= t_end) {
      KV_LOADT(buf ^ 1, t0 + AT_TK);
      asm volatile("cp.async.wait_group 1;" ::: "memory");
    } else {
      asm volatile("cp.async.wait_group 0;" ::: "memory");
    }
    __syncthreads();

    if (t0 <= tmax) {
      float sf[4][4];
#pragma unroll
      for (int j = 0; j < 4; j++)
#pragma unroll
        for (int q = 0; q < 4; q++) sf[j][q] = 0.f;

#pragma unroll
      for (int s = 0; s < 8; s++) {
        const int kb = s * 16 + 2 * tig;
        unsigned bk[4][2];
#pragma unroll
        for (int j = 0; j < 4; j++) {
          bk[j][0] = *(const unsigned*)&Ks[buf][j * 8 + g][kb];
          bk[j][1] = *(const unsigned*)&Ks[buf][j * 8 + g][kb + 8];
        }
#pragma unroll
        for (int j = 0; j < 4; j++) mma_f16(sf[j], qa[s], bk[j]);
      }

      if (t0 + AT_TK - 1 > row0) {
#pragma unroll
        for (int j = 0; j < 4; j++) {
          const int col = t0 + j * 8 + 2 * tig;
          if (col > row0 + g) sf[j][0] = -CUDART_INF_F;
          if (col + 1 > row0 + g) sf[j][1] = -CUDART_INF_F;
          if (col > row0 + g + 8) sf[j][2] = -CUDART_INF_F;
          if (col + 1 > row0 + g + 8) sf[j][3] = -CUDART_INF_F;
        }
      }

      float tm0 = sf[0][0], tm1 = sf[0][2];
#pragma unroll
      for (int j = 0; j < 4; j++) {
        tm0 = fmaxf(tm0, fmaxf(sf[j][0], sf[j][1]));
        tm1 = fmaxf(tm1, fmaxf(sf[j][2], sf[j][3]));
      }
      tm0 = fmaxf(tm0, __shfl_xor_sync(0xffffffffu, tm0, 1));
      tm0 = fmaxf(tm0, __shfl_xor_sync(0xffffffffu, tm0, 2));
      tm1 = fmaxf(tm1, __shfl_xor_sync(0xffffffffu, tm1, 1));
      tm1 = fmaxf(tm1, __shfl_xor_sync(0xffffffffu, tm1, 2));

      const float mn0 = fmaxf(m0v, tm0);
      const float mn1 = fmaxf(m1v, tm1);
      const float cr0 = __expf(m0v - mn0);
      const float cr1 = __expf(m1v - mn1);

      float ps0 = 0.f, ps1 = 0.f;
#pragma unroll
      for (int j = 0; j < 4; j++) {
        sf[j][0] = __expf(sf[j][0] - mn0);
        sf[j][1] = __expf(sf[j][1] - mn0);
        sf[j][2] = __expf(sf[j][2] - mn1);
        sf[j][3] = __expf(sf[j][3] - mn1);
        ps0 += sf[j][0] + sf[j][1];
        ps1 += sf[j][2] + sf[j][3];
      }
      ps0 += __shfl_xor_sync(0xffffffffu, ps0, 1);
      ps0 += __shfl_xor_sync(0xffffffffu, ps0, 2);
      ps1 += __shfl_xor_sync(0xffffffffu, ps1, 1);
      ps1 += __shfl_xor_sync(0xffffffffu, ps1, 2);

      l0 = l0 * cr0 + ps0;
      l1 = l1 * cr1 + ps1;
      m0v = mn0;
      m1v = mn1;

#pragma unroll
      for (int j2 = 0; j2 < 16; j2++) {
        oa[j2][0] *= cr0; oa[j2][1] *= cr0;
        oa[j2][2] *= cr1; oa[j2][3] *= cr1;
      }

#pragma unroll
      for (int j = 0; j < 4; j++) {
        __half2 p0 = __floats2half2_rn(sf[j][0], sf[j][1]);
        __half2 p1 = __floats2half2_rn(sf[j][2], sf[j][3]);
        Ps[warp][g][j * 4 + tig] = *(unsigned*)&p0;
        Ps[warp][g + 8][j * 4 + tig] = *(unsigned*)&p1;
      }
      __syncwarp();

#pragma unroll
      for (int s = 0; s < 2; s++) {
        unsigned pa[4];
        pa[0] = Ps[warp][g][s * 8 + tig];
        pa[1] = Ps[warp][g + 8][s * 8 + tig];
        pa[2] = Ps[warp][g][s * 8 + tig + 4];
        pa[3] = Ps[warp][g + 8][s * 8 + tig + 4];
        const uint32_t vrow =
            sVs + buf * KVB + (s * 16 + (lane & 15)) * (KLD * 2);
#pragma unroll
        for (int j2 = 0; j2 < 16; j2++) {
          unsigned bv[2];
          ldmx2t(bv[0], bv[1], vrow + j2 * 16);
          mma_f16(oa[j2], pa, bv);
        }
      }
    }
    __syncthreads();
  }

  const float inv0 = 1.0f / l0;
  const float inv1 = 1.0f / l1;
  __half* Ob = O + ((size_t)(b * L_ + row0) * H_ + h) * HD_;
#pragma unroll
  for (int j2 = 0; j2 < 16; j2++) {
    const int col = j2 * 8 + 2 * tig;
    *(__half2*)(Ob + (size_t)g * D_ + col) =
        __floats2half2_rn(oa[j2][0] * inv0, oa[j2][1] * inv0);
    *(__half2*)(Ob + (size_t)(g + 8) * D_ + col) =
        __floats2half2_rn(oa[j2][2] * inv1, oa[j2][3] * inv1);
  }
}

// ---------------------------------------------------------------------------
extern "C" void kernel_launch(void* const* d_in, const int* in_sizes, int n_in,
                              void* d_out, int out_size) {
  (void)in_sizes; (void)n_in; (void)out_size;
  const float* x  = (const float*)d_in[0];
  const float* wq = (const float*)d_in[1];
  const float* wk = (const float*)d_in[2];
  const float* wv = (const float*)d_in[3];
  const float* wo = (const float*)d_in[4];
  float* out = (float*)d_out;

  __half *qh, *kh, *vh, *xh, *wqh, *wkh, *wvh, *woh, *aoh;
  cudaGetSymbolAddress((void**)&qh, g_qh);
  cudaGetSymbolAddress((void**)&kh, g_kh);
  cudaGetSymbolAddress((void**)&vh, g_vh);
  cudaGetSymbolAddress((void**)&xh, g_xh);
  cudaGetSymbolAddress((void**)&wqh, g_wqh);
  cudaGetSymbolAddress((void**)&wkh, g_wkh);
  cudaGetSymbolAddress((void**)&wvh, g_wvh);
  cudaGetSymbolAddress((void**)&woh, g_woh);
  cudaGetSymbolAddress((void**)&aoh, g_aoh);

  const int M = B_ * L_;  // 4096

  // merged fp16 conversion of all GEMM operands
  {
    const int nx = (B_ * L_ * D_) / 4;
    const int nw = (D_ * D_) / 4;
    const int nkv = (KV_ * HD_ * D_) / 4;
    const int ntot = nx + 2 * nw + 2 * nkv;
    cvt_all_kernel<<<(ntot + 255) / 256, 256>>>(x, xh, nx, wq, wqh, nw, wo,
                                                woh, nw, wk, wkh, nkv, wv,
                                                wvh, nkv);
  }

  // Fused Q/K/V projections + fused RoPE epilogue: one launch, 768 tiles
  gemm_qkv<<<dim3(24, M / FBM), 256>>>(xh, wqh, wkh, wvh, qh, kh, vh, M, D_);

  // causal attention (fp16 tensor cores), heavy blocks first
  flash_attn_f16<<<dim3(L_ / AT_QB, H_, B_), 128>>>(qh, kh, vh, aoh);

  // output projection -> d_out
  gemm_single<<<dim3(D_ / FBN, M / FBM), 256>>>(aoh, woh, out, M, D_, D_);
}

// round 10
// speedup vs baseline: 1.8379x; 1.1321x over previous
#include <cuda_runtime.h>
#include <cuda_fp16.h>
#include <math_constants.h>
#include <cstdint>

#define B_ 2
#define L_ 2048
#define D_ 2048
#define H_ 16
#define KV_ 4
#define HD_ 128
#define REP_ (H_ / KV_)

// Scratch (allocation-free rule: device globals)
__device__ __half g_qh[(size_t)B_ * L_ * D_];           // 16 MB (roped q * scale)
__device__ __half g_kh[(size_t)B_ * L_ * KV_ * HD_];    // 4 MB  (roped k)
__device__ __half g_vh[(size_t)B_ * L_ * KV_ * HD_];    // 4 MB
__device__ __half g_xh[(size_t)B_ * L_ * D_];           // 16 MB
__device__ __half g_wqh[(size_t)D_ * D_];               // 8 MB
__device__ __half g_wkh[(size_t)KV_ * HD_ * D_];        // 2 MB
__device__ __half g_wvh[(size_t)KV_ * HD_ * D_];        // 2 MB
__device__ __half g_woh[(size_t)D_ * D_];               // 8 MB
__device__ __half g_aoh[(size_t)B_ * L_ * D_];          // 16 MB

// ---------------------------------------------------------------------------
// helpers
// ---------------------------------------------------------------------------
__device__ __forceinline__ void mma_f16(float c[4], const unsigned a[4],
                                        const unsigned b[2]) {
  asm volatile(
      "mma.sync.aligned.m16n8k16.row.col.f32.f16.f16.f32 "
      "{%0,%1,%2,%3}, {%4,%5,%6,%7}, {%8,%9}, {%0,%1,%2,%3};"
      : "+f"(c[0]), "+f"(c[1]), "+f"(c[2]), "+f"(c[3])
      : "r"(a[0]), "r"(a[1]), "r"(a[2]), "r"(a[3]), "r"(b[0]), "r"(b[1]));
}

__device__ __forceinline__ void ldmx4(unsigned r[4], uint32_t addr) {
  asm volatile(
      "ldmatrix.sync.aligned.m8n8.x4.shared.b16 {%0,%1,%2,%3}, [%4];"
      : "=r"(r[0]), "=r"(r[1]), "=r"(r[2]), "=r"(r[3]) : "r"(addr));
}

__device__ __forceinline__ void ldmx2t(unsigned& r0, unsigned& r1,
                                       uint32_t addr) {
  asm volatile(
      "ldmatrix.sync.aligned.m8n8.x2.trans.shared.b16 {%0,%1}, [%2];"
      : "=r"(r0), "=r"(r1) : "r"(addr));
}

__device__ __forceinline__ uint32_t smem_u32(const void* p) {
  uint32_t a;
  asm("{ .reg .u64 t; cvta.to.shared.u64 t, %1; cvt.u32.u64 %0, t; }"
      : "=r"(a) : "l"(p));
  return a;
}

__device__ __forceinline__ void cp_async16(uint32_t dst, const void* src) {
  asm volatile("cp.async.cg.shared.global [%0], [%1], 16;\n"
               :: "r"(dst), "l"(src) : "memory");
}

// ---------------------------------------------------------------------------
// fp16 tensor-core GEMM core, BK=64 + single-sync pipeline:
// 128x128 CTA tile, 256 threads (8 warps 2x4), warp tile 64x32,
// m16n8k16 + ldmatrix, 2-stage cp.async (dynamic smem, 72KB), ONE
// __syncthreads per iteration: [wait; sync; issue next loads; compute x4].
// FLD=72 halfs/row: 36 words == 4 mod 32 -> ldmatrix rows hit distinct banks.
// Epilogue modes: 0 = fp32 C; 1 = fp16 C; 2 = fp16 C + fused RoPE*scale.
// ---------------------------------------------------------------------------
#define FBM 128
#define FBN 128
#define FBK 64
#define FLD 72                       // halfs per row (64 + 8 pad)
#define GSTG (FBM * FLD)             // halfs per stage per matrix
#define STB (GSTG * 2)               // stage bytes (18432)
#define GT_SMEM (4 * STB)            // 2 stages x (A+B) = 73728 B

__device__ __forceinline__ void gemm_core(
    const __half* __restrict__ Ab, const __half* __restrict__ Wb,
    float* __restrict__ Cf, __half* __restrict__ Ch,
    int N, int Kd, int bm, int bn, int mode, float rscale, __half* dsm) {
  const int tid = threadIdx.x;
  const int warp = tid >> 5;
  const int lane = tid & 31;
  const int m0 = (warp >> 2) * 64;
  const int n0 = (warp & 3) * 32;

  const uint32_t sbA = smem_u32(dsm);
  const uint32_t sbB = sbA + 2 * STB;

  // cp.async map: per stage per matrix 128 rows x 8 chunks(16B) = 1024,
  // 256 threads -> 4 chunks each
  uint32_t dA[4];
  size_t sA[4];
#pragma unroll
  for (int i = 0; i < 4; i++) {
    const int e = tid + i * 256;
    const int row = e >> 3, c = e & 7;
    dA[i] = (uint32_t)(row * (FLD * 2) + c * 16);
    sA[i] = (size_t)row * Kd + c * 8;
  }

#define F16_LOAD(buf, k0)                                                   \
  do {                                                                      \
    _Pragma("unroll")                                                       \
    for (int i = 0; i < 4; i++)                                             \
      cp_async16(sbA + (buf)*STB + dA[i], Ab + sA[i] + (k0));               \
    _Pragma("unroll")                                                       \
    for (int i = 0; i < 4; i++)                                             \
      cp_async16(sbB + (buf)*STB + dA[i], Wb + sA[i] + (k0));               \
    asm volatile("cp.async.commit_group;" ::: "memory");                    \
  } while (0)

  const uint32_t a_off =
      (uint32_t)(((m0 + (lane & 15)) * FLD + ((lane >> 4) << 3)) * 2);
  const uint32_t b_off =
      (uint32_t)(((n0 + (lane & 7) + ((lane >> 4) & 1) * 8) * FLD +
                  ((lane >> 3) & 1) * 8) * 2);

  float acc[4][4][4];
#pragma unroll
  for (int i = 0; i < 4; i++)
#pragma unroll
    for (int j = 0; j < 4; j++)
#pragma unroll
      for (int q = 0; q < 4; q++) acc[i][j][q] = 0.f;

  const int nk = Kd / FBK;
  F16_LOAD(0, 0);

  for (int t = 0; t < nk; t++) {
    const int buf = t & 1;
    asm volatile("cp.async.wait_group 0;" ::: "memory");
    __syncthreads();
    if (t + 1 < nk) F16_LOAD(buf ^ 1, (t + 1) * FBK);

    const uint32_t aB = sbA + buf * STB + a_off;
    const uint32_t bB = sbB + buf * STB + b_off;
#pragma unroll
    for (int ks = 0; ks < 4; ks++) {
      const uint32_t ksb = ks * 32;  // 16 halfs = 32 bytes
      unsigned a[4][4], b[4][2];
#pragma unroll
      for (int i = 0; i < 4; i++) ldmx4(a[i], aB + i * (16 * FLD * 2) + ksb);
      {
        unsigned t4[4];
        ldmx4(t4, bB + ksb);
        b[0][0] = t4[0]; b[0][1] = t4[1]; b[1][0] = t4[2]; b[1][1] = t4[3];
        ldmx4(t4, bB + 16 * FLD * 2 + ksb);
        b[2][0] = t4[0]; b[2][1] = t4[1]; b[3][0] = t4[2]; b[3][1] = t4[3];
      }
#pragma unroll
      for (int i = 0; i < 4; i++)
#pragma unroll
        for (int j = 0; j < 4; j++) mma_f16(acc[i][j], a[i], b[j]);
    }
  }

  const int g = lane >> 2;
  const int tig = lane & 3;
  if (mode == 0) {
#pragma unroll
    for (int i = 0; i < 4; i++)
#pragma unroll
      for (int j = 0; j < 4; j++) {
        const size_t row1 = (size_t)(bm + m0 + i * 16 + g);
        const int col = bn + n0 + j * 8 + tig * 2;
        *(float2*)(Cf + row1 * N + col) = make_float2(acc[i][j][0], acc[i][j][1]);
        *(float2*)(Cf + (row1 + 8) * N + col) =
            make_float2(acc[i][j][2], acc[i][j][3]);
      }
  } else if (mode == 1) {
#pragma unroll
    for (int i = 0; i < 4; i++)
#pragma unroll
      for (int j = 0; j < 4; j++) {
        const size_t row1 = (size_t)(bm + m0 + i * 16 + g);
        const int col = bn + n0 + j * 8 + tig * 2;
        *(__half2*)(Ch + row1 * N + col) =
            __floats2half2_rn(acc[i][j][0], acc[i][j][1]);
        *(__half2*)(Ch + (row1 + 8) * N + col) =
            __floats2half2_rn(acc[i][j][2], acc[i][j][3]);
      }
  } else {
    // mode 2: fused RoPE (interleaved-pair) + scale, fp16 out
    float invf[4];
#pragma unroll
    for (int j = 0; j < 4; j++) {
      const int p = ((n0 + j * 8 + tig * 2) & (HD_ - 1)) >> 1;
      invf[j] = expf(-(float)p * (2.0f / HD_) * 9.210340371976184f);
    }
#pragma unroll
    for (int i = 0; i < 4; i++) {
      const int r1 = bm + m0 + i * 16 + g;
      const float pos1 = (float)(r1 & (L_ - 1));
      const float pos2 = (float)((r1 + 8) & (L_ - 1));
#pragma unroll
      for (int j = 0; j < 4; j++) {
        const int col = bn + n0 + j * 8 + tig * 2;
        float s1, c1, s2, c2;
        sincosf(pos1 * invf[j], &s1, &c1);
        sincosf(pos2 * invf[j], &s2, &c2);
        const float x1 = acc[i][j][0], x2 = acc[i][j][1];
        const float y1 = acc[i][j][2], y2 = acc[i][j][3];
        *(__half2*)(Ch + (size_t)r1 * N + col) = __floats2half2_rn(
            (x1 * c1 - x2 * s1) * rscale, (x1 * s1 + x2 * c1) * rscale);
        *(__half2*)(Ch + (size_t)(r1 + 8) * N + col) = __floats2half2_rn(
            (y1 * c2 - y2 * s2) * rscale, (y1 * s2 + y2 * c2) * rscale);
      }
    }
  }
}

// Fused QKV projection with fused RoPE epilogues:
// blockIdx.x 0..15 -> Q tile (rope*scale), 16..19 -> K (rope), 20..23 -> V.
__global__ __launch_bounds__(256, 2)
void gemm_qkv(const __half* __restrict__ xh, const __half* __restrict__ wqh,
              const __half* __restrict__ wkh, const __half* __restrict__ wvh,
              __half* __restrict__ qh, __half* __restrict__ kh,
              __half* __restrict__ vh, int M, int Kd) {
  extern __shared__ __half dsm[];
  const int bxx = blockIdx.x;
  const int bm = blockIdx.y * FBM;

  const __half* W;
  __half* Ch;
  int N, bn, mode;
  float rscale;
  if (bxx < 16) {
    W = wqh; Ch = qh; N = D_; bn = bxx * FBN; mode = 2;
    rscale = 0.088388347648318447f;  // 1/sqrt(128)
  } else if (bxx < 20) {
    W = wkh; Ch = kh; N = KV_ * HD_; bn = (bxx - 16) * FBN; mode = 2;
    rscale = 1.0f;
  } else {
    W = wvh; Ch = vh; N = KV_ * HD_; bn = (bxx - 20) * FBN; mode = 1;
    rscale = 1.0f;
  }
  gemm_core(xh + (size_t)bm * Kd, W + (size_t)bn * Kd, nullptr, Ch, N, Kd, bm,
            bn, mode, rscale, dsm);
}

// Single GEMM (O projection): C fp32.
__global__ __launch_bounds__(256, 2)
void gemm_single(const __half* __restrict__ A, const __half* __restrict__ W,
                 float* __restrict__ C, int M, int N, int Kd) {
  extern __shared__ __half dsm[];
  const int bm = blockIdx.y * FBM;
  const int bn = blockIdx.x * FBN;
  gemm_core(A + (size_t)bm * Kd, W + (size_t)bn * Kd, C, nullptr, N, Kd, bm,
            bn, 0, 1.0f, dsm);
}

// ---------------------------------------------------------------------------
// merged fp32 -> fp16 convert over 5 segments (x, wq, wo, wk, wv)
// ---------------------------------------------------------------------------
__global__ void cvt_all_kernel(const float* s0, __half* d0, int n0,
                               const float* s1, __half* d1, int n1,
                               const float* s2, __half* d2, int n2,
                               const float* s3, __half* d3, int n3,
                               const float* s4, __half* d4, int n4t) {
  int i = blockIdx.x * blockDim.x + threadIdx.x;
  const float* s;
  __half* d;
  if (i < n0) { s = s0; d = d0; }
  else if ((i -= n0) < n1) { s = s1; d = d1; }
  else if ((i -= n1) < n2) { s = s2; d = d2; }
  else if ((i -= n2) < n3) { s = s3; d = d3; }
  else if ((i -= n3) < n4t) { s = s4; d = d4; }
  else return;
  float4 v = ((const float4*)s)[i];
  __half2 lo = __floats2half2_rn(v.x, v.y);
  __half2 hi = __floats2half2_rn(v.z, v.w);
  ((uint2*)d)[i] = make_uint2(*(unsigned*)&lo, *(unsigned*)&hi);
}

// ---------------------------------------------------------------------------
// fp16 tensor-core causal flash attention (unchanged from round 9).
// ---------------------------------------------------------------------------
#define AT_TK 32
#define AT_WQ 16
#define AT_WARPS 4
#define AT_QB (AT_WQ * AT_WARPS)   // 64
#define KLD 136                    // halfs per K/V smem row (128 + 8)

__global__ __launch_bounds__(128, 3)
void flash_attn_f16(const __half* __restrict__ Qh, const __half* __restrict__ Kh,
                    const __half* __restrict__ Vh, __half* __restrict__ O) {
  __shared__ __half Ks[2][AT_TK][KLD];
  __shared__ __half Vs[2][AT_TK][KLD];
  __shared__ unsigned Ps[AT_WARPS][16][20];

  const int b = blockIdx.z;
  const int h = blockIdx.y;
  const int r0 = (gridDim.x - 1 - blockIdx.x) * AT_QB;  // heavy blocks first
  const int kvh = h / REP_;
  const int warp = threadIdx.x >> 5;
  const int lane = threadIdx.x & 31;
  const int g = lane >> 2;
  const int tig = lane & 3;
  const int row0 = r0 + warp * AT_WQ;

  const uint32_t sKs = smem_u32(&Ks[0][0][0]);
  const uint32_t sVs = smem_u32(&Vs[0][0][0]);
  const uint32_t KVB = AT_TK * KLD * 2;

  unsigned qa[8][4];
  {
    const __half* Qb = Qh + ((size_t)(b * L_ + row0) * H_ + h) * HD_;
#pragma unroll
    for (int s = 0; s < 8; s++) {
      const int k0 = s * 16 + 2 * tig;
      qa[s][0] = *(const unsigned*)(Qb + (size_t)g * D_ + k0);
      qa[s][1] = *(const unsigned*)(Qb + (size_t)(g + 8) * D_ + k0);
      qa[s][2] = *(const unsigned*)(Qb + (size_t)g * D_ + k0 + 8);
      qa[s][3] = *(const unsigned*)(Qb + (size_t)(g + 8) * D_ + k0 + 8);
    }
  }

  float m0v = -CUDART_INF_F, m1v = -CUDART_INF_F;
  float l0 = 0.f, l1 = 0.f;
  float oa[16][4];
#pragma unroll
  for (int j = 0; j < 16; j++)
#pragma unroll
    for (int q = 0; q < 4; q++) oa[j][q] = 0.f;

  uint32_t kdst[4];
  size_t ksrc[4];
#pragma unroll
  for (int i = 0; i < 4; i++) {
    int e = threadIdx.x + i * 128;
    int row = e >> 4, c = e & 15;
    kdst[i] = (uint32_t)(row * (KLD * 2) + c * 16);
    ksrc[i] = ((size_t)(b * L_ + row) * KV_ + kvh) * HD_ + c * 8;
  }

#define KV_LOADT(st, t0)                                                    \
  do {                                                                      \
    _Pragma("unroll")                                                       \
    for (int i = 0; i < 4; i++) {                                           \
      size_t sofs = ksrc[i] + (size_t)(t0) * (KV_ * HD_);                   \
      cp_async16(sKs + (st) * KVB + kdst[i], Kh + sofs);                    \
      cp_async16(sVs + (st) * KVB + kdst[i], Vh + sofs);                    \
    }                                                                       \
    asm volatile("cp.async.commit_group;" ::: "memory");                    \
  } while (0)

  const int tmax = row0 + AT_WQ - 1;
  const int t_end = r0 + AT_QB - 1;

  KV_LOADT(0, 0);

  for (int t0 = 0; t0 <= t_end; t0 += AT_TK) {
    const int buf = (t0 >> 5) & 1;
    if (t0 + AT_TK <= t_end) {
      KV_LOADT(buf ^ 1, t0 + AT_TK);
      asm volatile("cp.async.wait_group 1;" ::: "memory");
    } else {
      asm volatile("cp.async.wait_group 0;" ::: "memory");
    }
    __syncthreads();

    if (t0 <= tmax) {
      float sf[4][4];
#pragma unroll
      for (int j = 0; j < 4; j++)
#pragma unroll
        for (int q = 0; q < 4; q++) sf[j][q] = 0.f;

#pragma unroll
      for (int s = 0; s < 8; s++) {
        const int kb = s * 16 + 2 * tig;
        unsigned bk[4][2];
#pragma unroll
        for (int j = 0; j < 4; j++) {
          bk[j][0] = *(const unsigned*)&Ks[buf][j * 8 + g][kb];
          bk[j][1] = *(const unsigned*)&Ks[buf][j * 8 + g][kb + 8];
        }
#pragma unroll
        for (int j = 0; j < 4; j++) mma_f16(sf[j], qa[s], bk[j]);
      }

      if (t0 + AT_TK - 1 > row0) {
#pragma unroll
        for (int j = 0; j < 4; j++) {
          const int col = t0 + j * 8 + 2 * tig;
          if (col > row0 + g) sf[j][0] = -CUDART_INF_F;
          if (col + 1 > row0 + g) sf[j][1] = -CUDART_INF_F;
          if (col > row0 + g + 8) sf[j][2] = -CUDART_INF_F;
          if (col + 1 > row0 + g + 8) sf[j][3] = -CUDART_INF_F;
        }
      }

      float tm0 = sf[0][0], tm1 = sf[0][2];
#pragma unroll
      for (int j = 0; j < 4; j++) {
        tm0 = fmaxf(tm0, fmaxf(sf[j][0], sf[j][1]));
        tm1 = fmaxf(tm1, fmaxf(sf[j][2], sf[j][3]));
      }
      tm0 = fmaxf(tm0, __shfl_xor_sync(0xffffffffu, tm0, 1));
      tm0 = fmaxf(tm0, __shfl_xor_sync(0xffffffffu, tm0, 2));
      tm1 = fmaxf(tm1, __shfl_xor_sync(0xffffffffu, tm1, 1));
      tm1 = fmaxf(tm1, __shfl_xor_sync(0xffffffffu, tm1, 2));

      const float mn0 = fmaxf(m0v, tm0);
      const float mn1 = fmaxf(m1v, tm1);
      const float cr0 = __expf(m0v - mn0);
      const float cr1 = __expf(m1v - mn1);

      float ps0 = 0.f, ps1 = 0.f;
#pragma unroll
      for (int j = 0; j < 4; j++) {
        sf[j][0] = __expf(sf[j][0] - mn0);
        sf[j][1] = __expf(sf[j][1] - mn0);
        sf[j][2] = __expf(sf[j][2] - mn1);
        sf[j][3] = __expf(sf[j][3] - mn1);
        ps0 += sf[j][0] + sf[j][1];
        ps1 += sf[j][2] + sf[j][3];
      }
      ps0 += __shfl_xor_sync(0xffffffffu, ps0, 1);
      ps0 += __shfl_xor_sync(0xffffffffu, ps0, 2);
      ps1 += __shfl_xor_sync(0xffffffffu, ps1, 1);
      ps1 += __shfl_xor_sync(0xffffffffu, ps1, 2);

      l0 = l0 * cr0 + ps0;
      l1 = l1 * cr1 + ps1;
      m0v = mn0;
      m1v = mn1;

#pragma unroll
      for (int j2 = 0; j2 < 16; j2++) {
        oa[j2][0] *= cr0; oa[j2][1] *= cr0;
        oa[j2][2] *= cr1; oa[j2][3] *= cr1;
      }

#pragma unroll
      for (int j = 0; j < 4; j++) {
        __half2 p0 = __floats2half2_rn(sf[j][0], sf[j][1]);
        __half2 p1 = __floats2half2_rn(sf[j][2], sf[j][3]);
        Ps[warp][g][j * 4 + tig] = *(unsigned*)&p0;
        Ps[warp][g + 8][j * 4 + tig] = *(unsigned*)&p1;
      }
      __syncwarp();

#pragma unroll
      for (int s = 0; s < 2; s++) {
        unsigned pa[4];
        pa[0] = Ps[warp][g][s * 8 + tig];
        pa[1] = Ps[warp][g + 8][s * 8 + tig];
        pa[2] = Ps[warp][g][s * 8 + tig + 4];
        pa[3] = Ps[warp][g + 8][s * 8 + tig + 4];
        const uint32_t vrow =
            sVs + buf * KVB + (s * 16 + (lane & 15)) * (KLD * 2);
#pragma unroll
        for (int j2 = 0; j2 < 16; j2++) {
          unsigned bv[2];
          ldmx2t(bv[0], bv[1], vrow + j2 * 16);
          mma_f16(oa[j2], pa, bv);
        }
      }
    }
    __syncthreads();
  }

  const float inv0 = 1.0f / l0;
  const float inv1 = 1.0f / l1;
  __half* Ob = O + ((size_t)(b * L_ + row0) * H_ + h) * HD_;
#pragma unroll
  for (int j2 = 0; j2 < 16; j2++) {
    const int col = j2 * 8 + 2 * tig;
    *(__half2*)(Ob + (size_t)g * D_ + col) =
        __floats2half2_rn(oa[j2][0] * inv0, oa[j2][1] * inv0);
    *(__half2*)(Ob + (size_t)(g + 8) * D_ + col) =
        __floats2half2_rn(oa[j2][2] * inv1, oa[j2][3] * inv1);
  }
}

// ---------------------------------------------------------------------------
extern "C" void kernel_launch(void* const* d_in, const int* in_sizes, int n_in,
                              void* d_out, int out_size) {
  (void)in_sizes; (void)n_in; (void)out_size;
  const float* x  = (const float*)d_in[0];
  const float* wq = (const float*)d_in[1];
  const float* wk = (const float*)d_in[2];
  const float* wv = (const float*)d_in[3];
  const float* wo = (const float*)d_in[4];
  float* out = (float*)d_out;

  __half *qh, *kh, *vh, *xh, *wqh, *wkh, *wvh, *woh, *aoh;
  cudaGetSymbolAddress((void**)&qh, g_qh);
  cudaGetSymbolAddress((void**)&kh, g_kh);
  cudaGetSymbolAddress((void**)&vh, g_vh);
  cudaGetSymbolAddress((void**)&xh, g_xh);
  cudaGetSymbolAddress((void**)&wqh, g_wqh);
  cudaGetSymbolAddress((void**)&wkh, g_wkh);
  cudaGetSymbolAddress((void**)&wvh, g_wvh);
  cudaGetSymbolAddress((void**)&woh, g_woh);
  cudaGetSymbolAddress((void**)&aoh, g_aoh);

  cudaFuncSetAttribute(gemm_qkv, cudaFuncAttributeMaxDynamicSharedMemorySize,
                       GT_SMEM);
  cudaFuncSetAttribute(gemm_single,
                       cudaFuncAttributeMaxDynamicSharedMemorySize, GT_SMEM);

  const int M = B_ * L_;  // 4096

  // merged fp16 conversion of all GEMM operands
  {
    const int nx = (B_ * L_ * D_) / 4;
    const int nw = (D_ * D_) / 4;
    const int nkv = (KV_ * HD_ * D_) / 4;
    const int ntot = nx + 2 * nw + 2 * nkv;
    cvt_all_kernel<<<(ntot + 255) / 256, 256>>>(x, xh, nx, wq, wqh, nw, wo,
                                                woh, nw, wk, wkh, nkv, wv,
                                                wvh, nkv);
  }

  // Fused Q/K/V projections + fused RoPE epilogue: one launch, 768 tiles
  gemm_qkv<<<dim3(24, M / FBM), 256, GT_SMEM>>>(xh, wqh, wkh, wvh, qh, kh, vh,
                                                M, D_);

  // causal attention (fp16 tensor cores), heavy blocks first
  flash_attn_f16<<<dim3(L_ / AT_QB, H_, B_), 128>>>(qh, kh, vh, aoh);

  // output projection -> d_out
  gemm_single<<<dim3(D_ / FBN, M / FBM), 256, GT_SMEM>>>(aoh, woh, out, M, D_,
                                                         D_);
}